// round 1
// baseline (speedup 1.0000x reference)
#include <cuda_runtime.h>
#include <cuda_bf16.h>

#define N_NODES 50000
#define N_EDGES 800000
#define NT      850000      // edges + self loops
#define N_GRAPHS 256
#define F_IN    41
#define C1      256         // heads*hid layer1 output
#define C2      256         // layer2 output
#define NEG_SLOPE 0.2f

// ---------------- scratch (device globals; no allocation allowed) ----------------
__device__ __align__(16) float    g_h1[N_NODES * C1];
__device__ float    g_al_s1[N_NODES * 2];
__device__ float    g_al_d1[N_NODES * 2];
__device__ unsigned g_m1[N_NODES * 2];
__device__ float    g_den1[N_NODES * 2];
__device__ float    g_e1[NT * 2];
__device__ __align__(16) float    g_out1[N_NODES * C1];
__device__ __align__(16) float    g_h2[N_NODES * C2];
__device__ float    g_al_s2[N_NODES];
__device__ float    g_al_d2[N_NODES];
__device__ unsigned g_m2[N_NODES];
__device__ float    g_den2[N_NODES];
__device__ float    g_e2[NT];
__device__ __align__(16) float    g_out2[N_NODES * C2];
__device__ float    g_pool[N_GRAPHS * 256];
__device__ float    g_cnt[N_GRAPHS];
__device__ float    g_fc1[N_GRAPHS * 1024];

// order-preserving float <-> uint for atomicMax
__device__ __forceinline__ unsigned f2o(float f) {
    unsigned u = __float_as_uint(f);
    return (u & 0x80000000u) ? ~u : (u | 0x80000000u);
}
__device__ __forceinline__ float o2f(unsigned u) {
    return (u & 0x80000000u) ? __uint_as_float(u ^ 0x80000000u) : __uint_as_float(~u);
}

// ---------------- layer 1 GEMM + attention logits (fused) ----------------
// one block (256 thr) per node: h1 = x @ W1 ; al = <h1, a_{src,dst}> per head
__global__ void k_gemm1(const float* __restrict__ x, const float* __restrict__ W1,
                        const float* __restrict__ a_s, const float* __restrict__ a_d) {
    int n = blockIdx.x;
    int c = threadIdx.x;
    __shared__ float xs[F_IN];
    if (c < F_IN) xs[c] = x[n * F_IN + c];
    __syncthreads();
    float acc = 0.f;
#pragma unroll
    for (int k = 0; k < F_IN; k++) acc += xs[k] * W1[k * C1 + c];
    g_h1[n * C1 + c] = acc;

    int head = c >> 7, ch = c & 127;
    float vs = acc * a_s[head * 128 + ch];
    float vd = acc * a_d[head * 128 + ch];
#pragma unroll
    for (int o = 16; o > 0; o >>= 1) {
        vs += __shfl_down_sync(0xFFFFFFFFu, vs, o);
        vd += __shfl_down_sync(0xFFFFFFFFu, vd, o);
    }
    __shared__ float ss[8], sd[8];
    int w = c >> 5;
    if ((c & 31) == 0) { ss[w] = vs; sd[w] = vd; }
    __syncthreads();
    if (c < 2) {
        float s = 0.f, d2 = 0.f;
        for (int w2 = c * 4; w2 < c * 4 + 4; w2++) { s += ss[w2]; d2 += sd[w2]; }
        g_al_s1[n * 2 + c] = s;
        g_al_d1[n * 2 + c] = d2;
    }
}

// ---------------- edge passes, layer 1 (2 heads) ----------------
__global__ void k_edgeA1(const int* __restrict__ src, const int* __restrict__ dst) {
    int idx = blockIdx.x * blockDim.x + threadIdx.x;
    if (idx >= NT * 2) return;
    int i = idx >> 1, h = idx & 1;
    int s, d;
    if (i < N_EDGES) { s = src[i]; d = dst[i]; } else { s = d = i - N_EDGES; }
    float e = g_al_s1[s * 2 + h] + g_al_d1[d * 2 + h];
    e = e > 0.f ? e : NEG_SLOPE * e;
    g_e1[i * 2 + h] = e;
    atomicMax(&g_m1[d * 2 + h], f2o(e));
}

__global__ void k_edgeB1(const int* __restrict__ src, const int* __restrict__ dst) {
    int idx = blockIdx.x * blockDim.x + threadIdx.x;
    if (idx >= NT * 2) return;
    int i = idx >> 1, h = idx & 1;
    int d;
    if (i < N_EDGES) { d = dst[i]; } else { d = i - N_EDGES; }
    float ex = __expf(g_e1[i * 2 + h] - o2f(g_m1[d * 2 + h]));
    g_e1[i * 2 + h] = ex;
    atomicAdd(&g_den1[d * 2 + h], ex);
}

// one block (256 thr) per edge: out1[dst] += alpha * h1[src]
__global__ void k_edgeC1(const int* __restrict__ src, const int* __restrict__ dst) {
    int i = blockIdx.x;
    int c = threadIdx.x;
    int s, d;
    if (i < N_EDGES) { s = src[i]; d = dst[i]; } else { s = d = i - N_EDGES; }
    int h = c >> 7;
    float alpha = g_e1[i * 2 + h] / (g_den1[d * 2 + h] + 1e-16f);
    atomicAdd(&g_out1[d * C1 + c], alpha * g_h1[s * C1 + c]);
}

// ---------------- elementwise bias + relu (in place) ----------------
__global__ void k_biasrelu(float* __restrict__ buf, const float* __restrict__ b) {
    int idx = blockIdx.x * blockDim.x + threadIdx.x;
    if (idx >= N_NODES * 256) return;
    float v = buf[idx] + b[idx & 255];
    buf[idx] = v > 0.f ? v : 0.f;
}

// ---------------- SGEMM: g_h2 = g_out1(M x 256) @ W2(256 x 256) ----------------
#define BM 64
#define BN 64
#define BK 16
__global__ void k_gemm2(const float* __restrict__ A, const float* __restrict__ B,
                        float* __restrict__ C, int M) {
    __shared__ __align__(16) float As[BK][BM];
    __shared__ __align__(16) float Bs[BK][BN];
    int bm = blockIdx.x * BM, bn = blockIdx.y * BN;
    int tid = threadIdx.x;                 // 256 threads
    int tr = tid >> 4, tc = tid & 15;      // 16x16 thread grid, 4x4 per thread
    float acc[4][4] = {};
    int ar = tid >> 2, ac = (tid & 3) * 4; // A tile load mapping
    int br = tid >> 4, bc = (tid & 15) * 4;
    for (int k0 = 0; k0 < 256; k0 += BK) {
        float4 av;
        if (bm + ar < M) av = *(const float4*)&A[(bm + ar) * 256 + k0 + ac];
        else av = make_float4(0.f, 0.f, 0.f, 0.f);
        As[ac + 0][ar] = av.x; As[ac + 1][ar] = av.y;
        As[ac + 2][ar] = av.z; As[ac + 3][ar] = av.w;
        float4 bv = *(const float4*)&B[(k0 + br) * 256 + bn + bc];
        *(float4*)&Bs[br][bc] = bv;
        __syncthreads();
#pragma unroll
        for (int kk = 0; kk < BK; kk++) {
            float a[4], b[4];
#pragma unroll
            for (int i = 0; i < 4; i++) a[i] = As[kk][tr * 4 + i];
#pragma unroll
            for (int j = 0; j < 4; j++) b[j] = Bs[kk][tc * 4 + j];
#pragma unroll
            for (int i = 0; i < 4; i++)
#pragma unroll
                for (int j = 0; j < 4; j++) acc[i][j] += a[i] * b[j];
        }
        __syncthreads();
    }
#pragma unroll
    for (int i = 0; i < 4; i++) {
        int r = bm + tr * 4 + i;
        if (r < M) {
#pragma unroll
            for (int j = 0; j < 4; j++) C[r * 256 + bn + tc * 4 + j] = acc[i][j];
        }
    }
}

// ---------------- layer 2 attention logits (1 head, C=256), one warp per node ----------------
__global__ void k_al2(const float* __restrict__ as2, const float* __restrict__ ad2) {
    int gidx = blockIdx.x * blockDim.x + threadIdx.x;
    int n = gidx >> 5;
    int lane = gidx & 31;
    if (n >= N_NODES) return;
    float vs = 0.f, vd = 0.f;
#pragma unroll
    for (int c = lane; c < 256; c += 32) {
        float h = g_h2[n * 256 + c];
        vs += h * as2[c];
        vd += h * ad2[c];
    }
#pragma unroll
    for (int o = 16; o > 0; o >>= 1) {
        vs += __shfl_down_sync(0xFFFFFFFFu, vs, o);
        vd += __shfl_down_sync(0xFFFFFFFFu, vd, o);
    }
    if (lane == 0) { g_al_s2[n] = vs; g_al_d2[n] = vd; }
}

// ---------------- edge passes, layer 2 (1 head) ----------------
__global__ void k_edgeA2(const int* __restrict__ src, const int* __restrict__ dst) {
    int i = blockIdx.x * blockDim.x + threadIdx.x;
    if (i >= NT) return;
    int s, d;
    if (i < N_EDGES) { s = src[i]; d = dst[i]; } else { s = d = i - N_EDGES; }
    float e = g_al_s2[s] + g_al_d2[d];
    e = e > 0.f ? e : NEG_SLOPE * e;
    g_e2[i] = e;
    atomicMax(&g_m2[d], f2o(e));
}

__global__ void k_edgeB2(const int* __restrict__ src, const int* __restrict__ dst) {
    int i = blockIdx.x * blockDim.x + threadIdx.x;
    if (i >= NT) return;
    int d;
    if (i < N_EDGES) { d = dst[i]; } else { d = i - N_EDGES; }
    float ex = __expf(g_e2[i] - o2f(g_m2[d]));
    g_e2[i] = ex;
    atomicAdd(&g_den2[d], ex);
}

__global__ void k_edgeC2(const int* __restrict__ src, const int* __restrict__ dst) {
    int i = blockIdx.x;
    int c = threadIdx.x;
    int s, d;
    if (i < N_EDGES) { s = src[i]; d = dst[i]; } else { s = d = i - N_EDGES; }
    float alpha = g_e2[i] / (g_den2[d] + 1e-16f);
    atomicAdd(&g_out2[d * C2 + c], alpha * g_h2[s * C2 + c]);
}

// ---------------- global mean pool ----------------
__global__ void k_pool(const int* __restrict__ batch) {
    int idx = blockIdx.x * blockDim.x + threadIdx.x;
    if (idx >= N_NODES * 256) return;
    int n = idx >> 8, c = idx & 255;
    int g = batch[n];
    atomicAdd(&g_pool[g * 256 + c], g_out2[idx]);
    if (c == 0) atomicAdd(&g_cnt[g], 1.0f);
}

// ---------------- MLP head ----------------
__global__ void k_mlp1(const float* __restrict__ fw, const float* __restrict__ fb) {
    int g = blockIdx.x >> 2, q = blockIdx.x & 3;
    int t = threadIdx.x;
    __shared__ float grow[256];
    float inv = 1.0f / fmaxf(g_cnt[g], 1.0f);
    grow[t] = g_pool[g * 256 + t] * inv;
    __syncthreads();
    int col = q * 256 + t;
    float acc = fb[col];
#pragma unroll 8
    for (int k = 0; k < 256; k++) acc += grow[k] * fw[k * 1024 + col];
    g_fc1[g * 1024 + col] = fmaxf(acc, 0.f);
}

__global__ void k_mlp2(const float* __restrict__ fw, const float* __restrict__ fb,
                       float* __restrict__ out) {
    int g = blockIdx.x;
    int t = threadIdx.x; // 128
    __shared__ float row[1024];
    for (int k = t; k < 1024; k += 128) row[k] = g_fc1[g * 1024 + k];
    __syncthreads();
    float acc = fb[t];
#pragma unroll 8
    for (int k = 0; k < 1024; k++) acc += row[k] * fw[k * 128 + t];
    out[g * 128 + t] = acc;
}

// ---------------- host launcher ----------------
static void* sym(const void* s) {
    void* p = nullptr;
    cudaGetSymbolAddress(&p, s);
    return p;
}

extern "C" void kernel_launch(void* const* d_in, const int* in_sizes, int n_in,
                              void* d_out, int out_size) {
    const float* x      = (const float*)d_in[0];
    const int*   src    = (const int*)d_in[1];
    const int*   dst    = (const int*)d_in[2];
    const int*   batch  = (const int*)d_in[3];
    const float* W1     = (const float*)d_in[4];
    const float* a_src1 = (const float*)d_in[5];
    const float* a_dst1 = (const float*)d_in[6];
    const float* b1     = (const float*)d_in[7];
    const float* W2     = (const float*)d_in[8];
    const float* a_src2 = (const float*)d_in[9];
    const float* a_dst2 = (const float*)d_in[10];
    const float* b2     = (const float*)d_in[11];
    const float* fc1_w  = (const float*)d_in[12];
    const float* fc1_b  = (const float*)d_in[13];
    const float* fc2_w  = (const float*)d_in[14];
    const float* fc2_b  = (const float*)d_in[15];
    float* out = (float*)d_out;

    // zero scratch (graph-capturable memset nodes)
    cudaMemsetAsync(sym(g_m1),   0, N_NODES * 2 * sizeof(unsigned));
    cudaMemsetAsync(sym(g_den1), 0, N_NODES * 2 * sizeof(float));
    cudaMemsetAsync(sym(g_out1), 0, (size_t)N_NODES * C1 * sizeof(float));
    cudaMemsetAsync(sym(g_m2),   0, N_NODES * sizeof(unsigned));
    cudaMemsetAsync(sym(g_den2), 0, N_NODES * sizeof(float));
    cudaMemsetAsync(sym(g_out2), 0, (size_t)N_NODES * C2 * sizeof(float));
    cudaMemsetAsync(sym(g_pool), 0, N_GRAPHS * 256 * sizeof(float));
    cudaMemsetAsync(sym(g_cnt),  0, N_GRAPHS * sizeof(float));

    float* d_h2 = (float*)sym(g_h2);
    float* d_o1 = (float*)sym(g_out1);
    float* d_o2 = (float*)sym(g_out2);

    // layer 1
    k_gemm1<<<N_NODES, 256>>>(x, W1, a_src1, a_dst1);
    k_edgeA1<<<(NT * 2 + 255) / 256, 256>>>(src, dst);
    k_edgeB1<<<(NT * 2 + 255) / 256, 256>>>(src, dst);
    k_edgeC1<<<NT, 256>>>(src, dst);
    k_biasrelu<<<(N_NODES * 256 + 255) / 256, 256>>>(d_o1, b1);

    // layer 2
    dim3 g2((N_NODES + BM - 1) / BM, 256 / BN);
    k_gemm2<<<g2, 256>>>(d_o1, W2, d_h2, N_NODES);
    k_al2<<<(N_NODES * 32 + 255) / 256, 256>>>(a_src2, a_dst2);
    k_edgeA2<<<(NT + 255) / 256, 256>>>(src, dst);
    k_edgeB2<<<(NT + 255) / 256, 256>>>(src, dst);
    k_edgeC2<<<NT, 256>>>(src, dst);
    k_biasrelu<<<(N_NODES * 256 + 255) / 256, 256>>>(d_o2, b2);

    // pool + MLP
    k_pool<<<(N_NODES * 256 + 255) / 256, 256>>>(batch);
    k_mlp1<<<N_GRAPHS * 4, 256>>>(fc1_w, fc1_b);
    k_mlp2<<<N_GRAPHS, 128>>>(fc2_w, fc2_b, out);
}

// round 2
// speedup vs baseline: 2.0830x; 2.0830x over previous
#include <cuda_runtime.h>
#include <cuda_bf16.h>

#define N_NODES 50000
#define N_EDGES 800000
#define NT      850000      // edges + self loops
#define N_GRAPHS 256
#define F_IN    41
#define C1      256         // heads*hid layer1 output
#define C2      256         // layer2 output
#define NEG_SLOPE 0.2f

// ---------------- scratch (device globals; no allocation allowed) ----------------
__device__ __align__(16) float    g_h1[N_NODES * C1];
__device__ float    g_al_s1[N_NODES * 2];
__device__ float    g_al_d1[N_NODES * 2];
__device__ unsigned g_m1[N_NODES * 2];
__device__ float    g_den1[N_NODES * 2];
__device__ float    g_e1[NT * 2];
__device__ __align__(16) float    g_out1[N_NODES * C1];
__device__ __align__(16) float    g_h2[N_NODES * C2];
__device__ float    g_al_s2[N_NODES];
__device__ float    g_al_d2[N_NODES];
__device__ unsigned g_m2[N_NODES];
__device__ float    g_den2[N_NODES];
__device__ float    g_e2[NT];
__device__ __align__(16) float    g_out2[N_NODES * C2];
__device__ __align__(16) float    g_pool[N_GRAPHS * 256];
__device__ float    g_cnt[N_GRAPHS];
__device__ float    g_fc1[N_GRAPHS * 1024];

// order-preserving float <-> uint for atomicMax
__device__ __forceinline__ unsigned f2o(float f) {
    unsigned u = __float_as_uint(f);
    return (u & 0x80000000u) ? ~u : (u | 0x80000000u);
}
__device__ __forceinline__ float o2f(unsigned u) {
    return (u & 0x80000000u) ? __uint_as_float(u ^ 0x80000000u) : __uint_as_float(~u);
}

// vectorized reduction: 4 floats per REDG lane (sm_90+)
__device__ __forceinline__ void red_add_v4(float* addr, float4 v) {
    asm volatile("red.global.add.v4.f32 [%0], {%1, %2, %3, %4};"
                 :: "l"(addr), "f"(v.x), "f"(v.y), "f"(v.z), "f"(v.w)
                 : "memory");
}

// ---------------- layer 1 GEMM + attention logits (fused) ----------------
// one block (256 thr) per node: h1 = x @ W1 ; al = <h1, a_{src,dst}> per head
__global__ void k_gemm1(const float* __restrict__ x, const float* __restrict__ W1,
                        const float* __restrict__ a_s, const float* __restrict__ a_d) {
    int n = blockIdx.x;
    int c = threadIdx.x;
    __shared__ float xs[F_IN];
    if (c < F_IN) xs[c] = x[n * F_IN + c];
    __syncthreads();
    float acc = 0.f;
#pragma unroll
    for (int k = 0; k < F_IN; k++) acc += xs[k] * W1[k * C1 + c];
    g_h1[n * C1 + c] = acc;

    int head = c >> 7, ch = c & 127;
    float vs = acc * a_s[head * 128 + ch];
    float vd = acc * a_d[head * 128 + ch];
#pragma unroll
    for (int o = 16; o > 0; o >>= 1) {
        vs += __shfl_down_sync(0xFFFFFFFFu, vs, o);
        vd += __shfl_down_sync(0xFFFFFFFFu, vd, o);
    }
    __shared__ float ss[8], sd[8];
    int w = c >> 5;
    if ((c & 31) == 0) { ss[w] = vs; sd[w] = vd; }
    __syncthreads();
    if (c < 2) {
        float s = 0.f, d2 = 0.f;
        for (int w2 = c * 4; w2 < c * 4 + 4; w2++) { s += ss[w2]; d2 += sd[w2]; }
        g_al_s1[n * 2 + c] = s;
        g_al_d1[n * 2 + c] = d2;
    }
}

// ---------------- edge passes, layer 1 (2 heads) ----------------
__global__ void k_edgeA1(const int* __restrict__ src, const int* __restrict__ dst) {
    int idx = blockIdx.x * blockDim.x + threadIdx.x;
    if (idx >= NT * 2) return;
    int i = idx >> 1, h = idx & 1;
    int s, d;
    if (i < N_EDGES) { s = src[i]; d = dst[i]; } else { s = d = i - N_EDGES; }
    float e = g_al_s1[s * 2 + h] + g_al_d1[d * 2 + h];
    e = e > 0.f ? e : NEG_SLOPE * e;
    g_e1[i * 2 + h] = e;
    atomicMax(&g_m1[d * 2 + h], f2o(e));
}

__global__ void k_edgeB1(const int* __restrict__ src, const int* __restrict__ dst) {
    int idx = blockIdx.x * blockDim.x + threadIdx.x;
    if (idx >= NT * 2) return;
    int i = idx >> 1, h = idx & 1;
    int d;
    if (i < N_EDGES) { d = dst[i]; } else { d = i - N_EDGES; }
    float ex = __expf(g_e1[i * 2 + h] - o2f(g_m1[d * 2 + h]));
    g_e1[i * 2 + h] = ex;
    atomicAdd(&g_den1[d * 2 + h], ex);
}

// 4 edges per 256-thread block; 64 float4-slots per edge.
// out1[dst] += alpha * h1[src], via red.global.add.v4.f32 (4 floats/REDG lane)
__global__ void k_edgeC1(const int* __restrict__ src, const int* __restrict__ dst) {
    int t = threadIdx.x;
    int sub = t >> 6;          // edge within block (0..3)
    int c4 = t & 63;           // float4 index (channels c4*4 .. c4*4+3)
    int i = blockIdx.x * 4 + sub;
    if (i >= NT) return;
    int s, d;
    if (i < N_EDGES) { s = src[i]; d = dst[i]; } else { s = d = i - N_EDGES; }
    int h = c4 >> 5;           // head: channels [0,128) -> 0, [128,256) -> 1
    float alpha = g_e1[i * 2 + h] / (g_den1[d * 2 + h] + 1e-16f);
    float4 hv = *(const float4*)&g_h1[s * C1 + c4 * 4];
    float4 v = make_float4(alpha * hv.x, alpha * hv.y, alpha * hv.z, alpha * hv.w);
    red_add_v4(&g_out1[d * C1 + c4 * 4], v);
}

// ---------------- elementwise bias + relu (in place) ----------------
__global__ void k_biasrelu(float* __restrict__ buf, const float* __restrict__ b) {
    int idx = blockIdx.x * blockDim.x + threadIdx.x;
    if (idx >= N_NODES * 256) return;
    float v = buf[idx] + b[idx & 255];
    buf[idx] = v > 0.f ? v : 0.f;
}

// ---------------- SGEMM: g_h2 = g_out1(M x 256) @ W2(256 x 256) ----------------
#define BM 64
#define BN 64
#define BK 16
__global__ void k_gemm2(const float* __restrict__ A, const float* __restrict__ B,
                        float* __restrict__ C, int M) {
    __shared__ __align__(16) float As[BK][BM];
    __shared__ __align__(16) float Bs[BK][BN];
    int bm = blockIdx.x * BM, bn = blockIdx.y * BN;
    int tid = threadIdx.x;                 // 256 threads
    int tr = tid >> 4, tc = tid & 15;      // 16x16 thread grid, 4x4 per thread
    float acc[4][4] = {};
    int ar = tid >> 2, ac = (tid & 3) * 4; // A tile load mapping
    int br = tid >> 4, bc = (tid & 15) * 4;
    for (int k0 = 0; k0 < 256; k0 += BK) {
        float4 av;
        if (bm + ar < M) av = *(const float4*)&A[(bm + ar) * 256 + k0 + ac];
        else av = make_float4(0.f, 0.f, 0.f, 0.f);
        As[ac + 0][ar] = av.x; As[ac + 1][ar] = av.y;
        As[ac + 2][ar] = av.z; As[ac + 3][ar] = av.w;
        float4 bv = *(const float4*)&B[(k0 + br) * 256 + bn + bc];
        *(float4*)&Bs[br][bc] = bv;
        __syncthreads();
#pragma unroll
        for (int kk = 0; kk < BK; kk++) {
            float a[4], b[4];
#pragma unroll
            for (int i = 0; i < 4; i++) a[i] = As[kk][tr * 4 + i];
#pragma unroll
            for (int j = 0; j < 4; j++) b[j] = Bs[kk][tc * 4 + j];
#pragma unroll
            for (int i = 0; i < 4; i++)
#pragma unroll
                for (int j = 0; j < 4; j++) acc[i][j] += a[i] * b[j];
        }
        __syncthreads();
    }
#pragma unroll
    for (int i = 0; i < 4; i++) {
        int r = bm + tr * 4 + i;
        if (r < M) {
#pragma unroll
            for (int j = 0; j < 4; j++) C[r * 256 + bn + tc * 4 + j] = acc[i][j];
        }
    }
}

// ---------------- layer 2 attention logits (1 head, C=256), one warp per node ----------------
__global__ void k_al2(const float* __restrict__ as2, const float* __restrict__ ad2) {
    int gidx = blockIdx.x * blockDim.x + threadIdx.x;
    int n = gidx >> 5;
    int lane = gidx & 31;
    if (n >= N_NODES) return;
    float vs = 0.f, vd = 0.f;
#pragma unroll
    for (int c = lane; c < 256; c += 32) {
        float h = g_h2[n * 256 + c];
        vs += h * as2[c];
        vd += h * ad2[c];
    }
#pragma unroll
    for (int o = 16; o > 0; o >>= 1) {
        vs += __shfl_down_sync(0xFFFFFFFFu, vs, o);
        vd += __shfl_down_sync(0xFFFFFFFFu, vd, o);
    }
    if (lane == 0) { g_al_s2[n] = vs; g_al_d2[n] = vd; }
}

// ---------------- edge passes, layer 2 (1 head) ----------------
__global__ void k_edgeA2(const int* __restrict__ src, const int* __restrict__ dst) {
    int i = blockIdx.x * blockDim.x + threadIdx.x;
    if (i >= NT) return;
    int s, d;
    if (i < N_EDGES) { s = src[i]; d = dst[i]; } else { s = d = i - N_EDGES; }
    float e = g_al_s2[s] + g_al_d2[d];
    e = e > 0.f ? e : NEG_SLOPE * e;
    g_e2[i] = e;
    atomicMax(&g_m2[d], f2o(e));
}

__global__ void k_edgeB2(const int* __restrict__ src, const int* __restrict__ dst) {
    int i = blockIdx.x * blockDim.x + threadIdx.x;
    if (i >= NT) return;
    int d;
    if (i < N_EDGES) { d = dst[i]; } else { d = i - N_EDGES; }
    float ex = __expf(g_e2[i] - o2f(g_m2[d]));
    g_e2[i] = ex;
    atomicAdd(&g_den2[d], ex);
}

// 4 edges per block; 64 float4-slots per edge; v4 reduction
__global__ void k_edgeC2(const int* __restrict__ src, const int* __restrict__ dst) {
    int t = threadIdx.x;
    int sub = t >> 6;
    int c4 = t & 63;
    int i = blockIdx.x * 4 + sub;
    if (i >= NT) return;
    int s, d;
    if (i < N_EDGES) { s = src[i]; d = dst[i]; } else { s = d = i - N_EDGES; }
    float alpha = g_e2[i] / (g_den2[d] + 1e-16f);
    float4 hv = *(const float4*)&g_h2[s * C2 + c4 * 4];
    float4 v = make_float4(alpha * hv.x, alpha * hv.y, alpha * hv.z, alpha * hv.w);
    red_add_v4(&g_out2[d * C2 + c4 * 4], v);
}

// ---------------- global mean pool (float4 reductions) ----------------
__global__ void k_pool(const int* __restrict__ batch) {
    int idx = blockIdx.x * blockDim.x + threadIdx.x;   // one thread per (node, c4)
    if (idx >= N_NODES * 64) return;
    int n = idx >> 6, c4 = idx & 63;
    int g = batch[n];
    float4 v = *(const float4*)&g_out2[n * 256 + c4 * 4];
    red_add_v4(&g_pool[g * 256 + c4 * 4], v);
    if (c4 == 0) atomicAdd(&g_cnt[g], 1.0f);
}

// ---------------- MLP head ----------------
__global__ void k_mlp1(const float* __restrict__ fw, const float* __restrict__ fb) {
    int g = blockIdx.x >> 2, q = blockIdx.x & 3;
    int t = threadIdx.x;
    __shared__ float grow[256];
    float inv = 1.0f / fmaxf(g_cnt[g], 1.0f);
    grow[t] = g_pool[g * 256 + t] * inv;
    __syncthreads();
    int col = q * 256 + t;
    float acc = fb[col];
#pragma unroll 8
    for (int k = 0; k < 256; k++) acc += grow[k] * fw[k * 1024 + col];
    g_fc1[g * 1024 + col] = fmaxf(acc, 0.f);
}

__global__ void k_mlp2(const float* __restrict__ fw, const float* __restrict__ fb,
                       float* __restrict__ out) {
    int g = blockIdx.x;
    int t = threadIdx.x; // 128
    __shared__ float row[1024];
    for (int k = t; k < 1024; k += 128) row[k] = g_fc1[g * 1024 + k];
    __syncthreads();
    float acc = fb[t];
#pragma unroll 8
    for (int k = 0; k < 1024; k++) acc += row[k] * fw[k * 128 + t];
    out[g * 128 + t] = acc;
}

// ---------------- host launcher ----------------
static void* sym(const void* s) {
    void* p = nullptr;
    cudaGetSymbolAddress(&p, s);
    return p;
}

extern "C" void kernel_launch(void* const* d_in, const int* in_sizes, int n_in,
                              void* d_out, int out_size) {
    const float* x      = (const float*)d_in[0];
    const int*   src    = (const int*)d_in[1];
    const int*   dst    = (const int*)d_in[2];
    const int*   batch  = (const int*)d_in[3];
    const float* W1     = (const float*)d_in[4];
    const float* a_src1 = (const float*)d_in[5];
    const float* a_dst1 = (const float*)d_in[6];
    const float* b1     = (const float*)d_in[7];
    const float* W2     = (const float*)d_in[8];
    const float* a_src2 = (const float*)d_in[9];
    const float* a_dst2 = (const float*)d_in[10];
    const float* b2     = (const float*)d_in[11];
    const float* fc1_w  = (const float*)d_in[12];
    const float* fc1_b  = (const float*)d_in[13];
    const float* fc2_w  = (const float*)d_in[14];
    const float* fc2_b  = (const float*)d_in[15];
    float* out = (float*)d_out;

    // zero scratch (graph-capturable memset nodes)
    cudaMemsetAsync(sym(g_m1),   0, N_NODES * 2 * sizeof(unsigned));
    cudaMemsetAsync(sym(g_den1), 0, N_NODES * 2 * sizeof(float));
    cudaMemsetAsync(sym(g_out1), 0, (size_t)N_NODES * C1 * sizeof(float));
    cudaMemsetAsync(sym(g_m2),   0, N_NODES * sizeof(unsigned));
    cudaMemsetAsync(sym(g_den2), 0, N_NODES * sizeof(float));
    cudaMemsetAsync(sym(g_out2), 0, (size_t)N_NODES * C2 * sizeof(float));
    cudaMemsetAsync(sym(g_pool), 0, N_GRAPHS * 256 * sizeof(float));
    cudaMemsetAsync(sym(g_cnt),  0, N_GRAPHS * sizeof(float));

    float* d_h2 = (float*)sym(g_h2);
    float* d_o1 = (float*)sym(g_out1);
    float* d_o2 = (float*)sym(g_out2);

    // layer 1
    k_gemm1<<<N_NODES, 256>>>(x, W1, a_src1, a_dst1);
    k_edgeA1<<<(NT * 2 + 255) / 256, 256>>>(src, dst);
    k_edgeB1<<<(NT * 2 + 255) / 256, 256>>>(src, dst);
    k_edgeC1<<<(NT + 3) / 4, 256>>>(src, dst);
    k_biasrelu<<<(N_NODES * 256 + 255) / 256, 256>>>(d_o1, b1);

    // layer 2
    dim3 g2((N_NODES + BM - 1) / BM, 256 / BN);
    k_gemm2<<<g2, 256>>>(d_o1, W2, d_h2, N_NODES);
    k_al2<<<(N_NODES * 32 + 255) / 256, 256>>>(a_src2, a_dst2);
    k_edgeA2<<<(NT + 255) / 256, 256>>>(src, dst);
    k_edgeB2<<<(NT + 255) / 256, 256>>>(src, dst);
    k_edgeC2<<<(NT + 3) / 4, 256>>>(src, dst);
    k_biasrelu<<<(N_NODES * 256 + 255) / 256, 256>>>(d_o2, b2);

    // pool + MLP
    k_pool<<<(N_NODES * 64 + 255) / 256, 256>>>(batch);
    k_mlp1<<<N_GRAPHS * 4, 256>>>(fc1_w, fc1_b);
    k_mlp2<<<N_GRAPHS, 128>>>(fc2_w, fc2_b, out);
}

// round 4
// speedup vs baseline: 3.6422x; 1.7485x over previous
#include <cuda_runtime.h>
#include <cuda_bf16.h>

#define N_NODES 50000
#define N_EDGES 800000
#define NT      850000      // edges + self loops
#define N_GRAPHS 256
#define F_IN    41
#define C1      256
#define C2      256
#define NEG_SLOPE 0.2f

// ---------------- scratch (device globals) ----------------
__device__ __align__(16) float g_h1[N_NODES * C1];
__device__ float g_al_s1[N_NODES * 2];
__device__ float g_al_d1[N_NODES * 2];
__device__ __align__(16) float g_out1[N_NODES * C1];
__device__ __align__(16) float g_h2[N_NODES * C2];
__device__ float g_al_s2[N_NODES];
__device__ float g_al_d2[N_NODES];
__device__ __align__(16) float g_pool[N_GRAPHS * 256];
__device__ float g_cnt[N_GRAPHS];
__device__ float g_fc1[N_GRAPHS * 1024];
// CSR
__device__ int g_deg[N_NODES];
__device__ int g_rowstart[N_NODES + 1];
__device__ int g_cursor[N_NODES];
__device__ int g_csrc[NT];

__device__ __forceinline__ void red_add_v4(float* addr, float4 v) {
    asm volatile("red.global.add.v4.f32 [%0], {%1, %2, %3, %4};"
                 :: "l"(addr), "f"(v.x), "f"(v.y), "f"(v.z), "f"(v.w)
                 : "memory");
}
__device__ __forceinline__ float lrelu(float e) { return e > 0.f ? e : NEG_SLOPE * e; }

// ---------------- CSR build ----------------
__global__ void k_deg(const int* __restrict__ dst) {
    int i = blockIdx.x * blockDim.x + threadIdx.x;
    if (i >= NT) return;
    int d = (i < N_EDGES) ? dst[i] : i - N_EDGES;
    atomicAdd(&g_deg[d], 1);
}

// single-block exclusive scan over g_deg -> g_rowstart, g_cursor
__global__ void k_scan() {
    __shared__ int warp_sums[32];
    __shared__ int s_carry;
    int tid = threadIdx.x, lane = tid & 31, w = tid >> 5;
    if (tid == 0) s_carry = 0;
    __syncthreads();
    for (int base = 0; base < N_NODES; base += 1024) {
        int i = base + tid;
        int v = (i < N_NODES) ? g_deg[i] : 0;
        int incl = v;
#pragma unroll
        for (int o = 1; o < 32; o <<= 1) {
            int t = __shfl_up_sync(0xFFFFFFFFu, incl, o);
            if (lane >= o) incl += t;
        }
        if (lane == 31) warp_sums[w] = incl;
        __syncthreads();
        if (w == 0) {
            int s = warp_sums[lane];
#pragma unroll
            for (int o = 1; o < 32; o <<= 1) {
                int t = __shfl_up_sync(0xFFFFFFFFu, s, o);
                if (lane >= o) s += t;
            }
            warp_sums[lane] = s;    // inclusive over warps
        }
        __syncthreads();
        int warp_off = (w == 0) ? 0 : warp_sums[w - 1];
        int excl = s_carry + warp_off + incl - v;
        if (i < N_NODES) { g_rowstart[i] = excl; g_cursor[i] = excl; }
        __syncthreads();
        if (tid == 0) s_carry += warp_sums[31];
        __syncthreads();
    }
    if (tid == 0) g_rowstart[N_NODES] = NT;
}

__global__ void k_fill(const int* __restrict__ src, const int* __restrict__ dst) {
    int i = blockIdx.x * blockDim.x + threadIdx.x;
    if (i >= NT) return;
    int s, d;
    if (i < N_EDGES) { s = src[i]; d = dst[i]; } else { s = d = i - N_EDGES; }
    int p = atomicAdd(&g_cursor[d], 1);
    g_csrc[p] = s;
}

// ---------------- layer 1 GEMM + attention logits (fused) ----------------
__global__ void k_gemm1(const float* __restrict__ x, const float* __restrict__ W1,
                        const float* __restrict__ a_s, const float* __restrict__ a_d) {
    int n = blockIdx.x;
    int c = threadIdx.x;
    __shared__ float xs[F_IN];
    if (c < F_IN) xs[c] = x[n * F_IN + c];
    __syncthreads();
    float acc = 0.f;
#pragma unroll
    for (int k = 0; k < F_IN; k++) acc += xs[k] * W1[k * C1 + c];
    g_h1[n * C1 + c] = acc;

    int head = c >> 7, ch = c & 127;
    float vs = acc * a_s[head * 128 + ch];
    float vd = acc * a_d[head * 128 + ch];
#pragma unroll
    for (int o = 16; o > 0; o >>= 1) {
        vs += __shfl_down_sync(0xFFFFFFFFu, vs, o);
        vd += __shfl_down_sync(0xFFFFFFFFu, vd, o);
    }
    __shared__ float ss[8], sd[8];
    int w = c >> 5;
    if ((c & 31) == 0) { ss[w] = vs; sd[w] = vd; }
    __syncthreads();
    if (c < 2) {
        float s = 0.f, d2 = 0.f;
        for (int w2 = c * 4; w2 < c * 4 + 4; w2++) { s += ss[w2]; d2 += sd[w2]; }
        g_al_s1[n * 2 + c] = s;
        g_al_d1[n * 2 + c] = d2;
    }
}

// ---------------- layer 1 fused softmax+gather, warp per dst node ----------------
__global__ void k_gat1(const float* __restrict__ b1) {
    int n = blockIdx.x * 8 + (threadIdx.x >> 5);
    int lane = threadIdx.x & 31;
    if (n >= N_NODES) return;
    int row = g_rowstart[n], end = g_rowstart[n + 1];
    float alD0 = g_al_d1[n * 2], alD1 = g_al_d1[n * 2 + 1];

    // pass1: max logit per head
    float m0 = -1e30f, m1 = -1e30f;
    for (int j = row + lane; j < end; j += 32) {
        int s = __ldg(&g_csrc[j]);
        m0 = fmaxf(m0, lrelu(__ldg(&g_al_s1[s * 2]) + alD0));
        m1 = fmaxf(m1, lrelu(__ldg(&g_al_s1[s * 2 + 1]) + alD1));
    }
#pragma unroll
    for (int o = 16; o > 0; o >>= 1) {
        m0 = fmaxf(m0, __shfl_xor_sync(0xFFFFFFFFu, m0, o));
        m1 = fmaxf(m1, __shfl_xor_sync(0xFFFFFFFFu, m1, o));
    }
    int h = lane >> 4;                 // this lane's channels' head
    float mh = h ? m1 : m0;
    float alDh = h ? alD1 : alD0;

    // pass2: exp weights + gather-accumulate (channels lane*8 .. lane*8+7)
    float den = 0.f;
    float acc[8] = {0.f, 0.f, 0.f, 0.f, 0.f, 0.f, 0.f, 0.f};
    for (int j0 = row; j0 < end; j0 += 32) {
        int sj = (j0 + lane < end) ? __ldg(&g_csrc[j0 + lane]) : 0;
        int cnt = min(32, end - j0);
        for (int k = 0; k < cnt; k++) {
            int s = __shfl_sync(0xFFFFFFFFu, sj, k);
            float e = lrelu(__ldg(&g_al_s1[s * 2 + h]) + alDh);
            float wgt = __expf(e - mh);
            den += wgt;
            const float4* hp = (const float4*)&g_h1[s * C1 + lane * 8];
            float4 v0 = hp[0], v1 = hp[1];
            acc[0] += wgt * v0.x; acc[1] += wgt * v0.y;
            acc[2] += wgt * v0.z; acc[3] += wgt * v0.w;
            acc[4] += wgt * v1.x; acc[5] += wgt * v1.y;
            acc[6] += wgt * v1.z; acc[7] += wgt * v1.w;
        }
    }
    float inv = 1.f / (den + 1e-16f);
    int c0 = lane * 8;
    float4 o0, o1;
    o0.x = fmaxf(acc[0] * inv + b1[c0 + 0], 0.f);
    o0.y = fmaxf(acc[1] * inv + b1[c0 + 1], 0.f);
    o0.z = fmaxf(acc[2] * inv + b1[c0 + 2], 0.f);
    o0.w = fmaxf(acc[3] * inv + b1[c0 + 3], 0.f);
    o1.x = fmaxf(acc[4] * inv + b1[c0 + 4], 0.f);
    o1.y = fmaxf(acc[5] * inv + b1[c0 + 5], 0.f);
    o1.z = fmaxf(acc[6] * inv + b1[c0 + 6], 0.f);
    o1.w = fmaxf(acc[7] * inv + b1[c0 + 7], 0.f);
    *(float4*)&g_out1[n * C1 + c0] = o0;
    *(float4*)&g_out1[n * C1 + c0 + 4] = o1;
}

// ---------------- SGEMM 128x128x16, 8x8 per thread: g_h2 = g_out1 @ W2 ----------------
#define BM2 128
#define BN2 128
#define BK2 16
__global__ void __launch_bounds__(256) k_gemm2(const float* __restrict__ A,
                                               const float* __restrict__ B,
                                               float* __restrict__ C, int M) {
    __shared__ __align__(16) float As[BK2][BM2];
    __shared__ __align__(16) float Bs[BK2][BN2];
    int bm = blockIdx.x * BM2, bn = blockIdx.y * BN2;
    int tid = threadIdx.x;
    int tr = tid >> 4, tc = tid & 15;
    float acc[8][8] = {};
    int ar = tid >> 2, ac = (tid & 3) * 4;
    int br = tid >> 5, bc = (tid & 31) * 4;
    for (int k0 = 0; k0 < 256; k0 += BK2) {
#pragma unroll
        for (int half = 0; half < 2; half++) {
            int r = ar + half * 64;
            float4 av = (bm + r < M) ? *(const float4*)&A[(size_t)(bm + r) * 256 + k0 + ac]
                                     : make_float4(0.f, 0.f, 0.f, 0.f);
            As[ac + 0][r] = av.x; As[ac + 1][r] = av.y;
            As[ac + 2][r] = av.z; As[ac + 3][r] = av.w;
        }
#pragma unroll
        for (int half = 0; half < 2; half++) {
            int r = br + half * 8;
            *(float4*)&Bs[r][bc] = *(const float4*)&B[(size_t)(k0 + r) * 256 + bn + bc];
        }
        __syncthreads();
#pragma unroll
        for (int kk = 0; kk < BK2; kk++) {
            float a[8], b[8];
#pragma unroll
            for (int i = 0; i < 8; i++) a[i] = As[kk][tr * 8 + i];
#pragma unroll
            for (int j = 0; j < 8; j++) b[j] = Bs[kk][tc * 8 + j];
#pragma unroll
            for (int i = 0; i < 8; i++)
#pragma unroll
                for (int j = 0; j < 8; j++) acc[i][j] += a[i] * b[j];
        }
        __syncthreads();
    }
#pragma unroll
    for (int i = 0; i < 8; i++) {
        int r = bm + tr * 8 + i;
        if (r < M) {
            *(float4*)&C[(size_t)r * 256 + bn + tc * 8]     =
                make_float4(acc[i][0], acc[i][1], acc[i][2], acc[i][3]);
            *(float4*)&C[(size_t)r * 256 + bn + tc * 8 + 4] =
                make_float4(acc[i][4], acc[i][5], acc[i][6], acc[i][7]);
        }
    }
}

// ---------------- layer 2 attention logits, warp per node ----------------
__global__ void k_al2(const float* __restrict__ as2, const float* __restrict__ ad2) {
    int gidx = blockIdx.x * blockDim.x + threadIdx.x;
    int n = gidx >> 5;
    int lane = gidx & 31;
    if (n >= N_NODES) return;
    float vs = 0.f, vd = 0.f;
#pragma unroll
    for (int c = lane; c < 256; c += 32) {
        float hv = g_h2[n * 256 + c];
        vs += hv * as2[c];
        vd += hv * ad2[c];
    }
#pragma unroll
    for (int o = 16; o > 0; o >>= 1) {
        vs += __shfl_down_sync(0xFFFFFFFFu, vs, o);
        vd += __shfl_down_sync(0xFFFFFFFFu, vd, o);
    }
    if (lane == 0) { g_al_s2[n] = vs; g_al_d2[n] = vd; }
}

// ---------------- layer 2 fused softmax+gather + bias/relu + pool, warp per dst ----------------
__global__ void k_gat2(const float* __restrict__ b2, const int* __restrict__ batch) {
    int n = blockIdx.x * 8 + (threadIdx.x >> 5);
    int lane = threadIdx.x & 31;
    if (n >= N_NODES) return;
    int row = g_rowstart[n], end = g_rowstart[n + 1];
    float alD = g_al_d2[n];

    float m = -1e30f;
    for (int j = row + lane; j < end; j += 32) {
        int s = __ldg(&g_csrc[j]);
        m = fmaxf(m, lrelu(__ldg(&g_al_s2[s]) + alD));
    }
#pragma unroll
    for (int o = 16; o > 0; o >>= 1)
        m = fmaxf(m, __shfl_xor_sync(0xFFFFFFFFu, m, o));

    float den = 0.f;
    float acc[8] = {0.f, 0.f, 0.f, 0.f, 0.f, 0.f, 0.f, 0.f};
    for (int j0 = row; j0 < end; j0 += 32) {
        int sj = (j0 + lane < end) ? __ldg(&g_csrc[j0 + lane]) : 0;
        int cnt = min(32, end - j0);
        for (int k = 0; k < cnt; k++) {
            int s = __shfl_sync(0xFFFFFFFFu, sj, k);
            float e = lrelu(__ldg(&g_al_s2[s]) + alD);
            float wgt = __expf(e - m);
            den += wgt;
            const float4* hp = (const float4*)&g_h2[s * C2 + lane * 8];
            float4 v0 = hp[0], v1 = hp[1];
            acc[0] += wgt * v0.x; acc[1] += wgt * v0.y;
            acc[2] += wgt * v0.z; acc[3] += wgt * v0.w;
            acc[4] += wgt * v1.x; acc[5] += wgt * v1.y;
            acc[6] += wgt * v1.z; acc[7] += wgt * v1.w;
        }
    }
    float inv = 1.f / (den + 1e-16f);
    int c0 = lane * 8;
    float4 o0, o1;
    o0.x = fmaxf(acc[0] * inv + b2[c0 + 0], 0.f);
    o0.y = fmaxf(acc[1] * inv + b2[c0 + 1], 0.f);
    o0.z = fmaxf(acc[2] * inv + b2[c0 + 2], 0.f);
    o0.w = fmaxf(acc[3] * inv + b2[c0 + 3], 0.f);
    o1.x = fmaxf(acc[4] * inv + b2[c0 + 4], 0.f);
    o1.y = fmaxf(acc[5] * inv + b2[c0 + 5], 0.f);
    o1.z = fmaxf(acc[6] * inv + b2[c0 + 6], 0.f);
    o1.w = fmaxf(acc[7] * inv + b2[c0 + 7], 0.f);
    int g = batch[n];
    red_add_v4(&g_pool[g * 256 + c0], o0);
    red_add_v4(&g_pool[g * 256 + c0 + 4], o1);
    if (lane == 0) atomicAdd(&g_cnt[g], 1.0f);
}

// ---------------- MLP head ----------------
__global__ void k_mlp1(const float* __restrict__ fw, const float* __restrict__ fb) {
    int g = blockIdx.x >> 2, q = blockIdx.x & 3;
    int t = threadIdx.x;
    __shared__ float grow[256];
    float inv = 1.0f / fmaxf(g_cnt[g], 1.0f);
    grow[t] = g_pool[g * 256 + t] * inv;
    __syncthreads();
    int col = q * 256 + t;
    float acc = fb[col];
#pragma unroll 8
    for (int k = 0; k < 256; k++) acc += grow[k] * fw[k * 1024 + col];
    g_fc1[g * 1024 + col] = fmaxf(acc, 0.f);
}

__global__ void k_mlp2(const float* __restrict__ fw, const float* __restrict__ fb,
                       float* __restrict__ out) {
    int g = blockIdx.x;
    int t = threadIdx.x; // 128
    __shared__ float row[1024];
    for (int k = t; k < 1024; k += 128) row[k] = g_fc1[g * 1024 + k];
    __syncthreads();
    float acc = fb[t];
#pragma unroll 8
    for (int k = 0; k < 1024; k++) acc += row[k] * fw[k * 128 + t];
    out[g * 128 + t] = acc;
}

// ---------------- host launcher ----------------
static void* sym(const void* s) {
    void* p = nullptr;
    cudaGetSymbolAddress(&p, s);
    return p;
}

extern "C" void kernel_launch(void* const* d_in, const int* in_sizes, int n_in,
                              void* d_out, int out_size) {
    const float* x      = (const float*)d_in[0];
    const int*   src    = (const int*)d_in[1];
    const int*   dst    = (const int*)d_in[2];
    const int*   batch  = (const int*)d_in[3];
    const float* W1     = (const float*)d_in[4];
    const float* a_src1 = (const float*)d_in[5];
    const float* a_dst1 = (const float*)d_in[6];
    const float* b1     = (const float*)d_in[7];
    const float* W2     = (const float*)d_in[8];
    const float* a_src2 = (const float*)d_in[9];
    const float* a_dst2 = (const float*)d_in[10];
    const float* b2     = (const float*)d_in[11];
    const float* fc1_w  = (const float*)d_in[12];
    const float* fc1_b  = (const float*)d_in[13];
    const float* fc2_w  = (const float*)d_in[14];
    const float* fc2_b  = (const float*)d_in[15];
    float* out = (float*)d_out;

    cudaMemsetAsync(sym(g_deg),  0, N_NODES * sizeof(int));
    cudaMemsetAsync(sym(g_pool), 0, N_GRAPHS * 256 * sizeof(float));
    cudaMemsetAsync(sym(g_cnt),  0, N_GRAPHS * sizeof(float));

    // CSR build
    k_deg<<<(NT + 255) / 256, 256>>>(dst);
    k_scan<<<1, 1024>>>();
    k_fill<<<(NT + 255) / 256, 256>>>(src, dst);

    // layer 1
    k_gemm1<<<N_NODES, 256>>>(x, W1, a_src1, a_dst1);
    k_gat1<<<(N_NODES + 7) / 8, 256>>>(b1);

    // layer 2
    float* d_o1 = (float*)sym(g_out1);
    float* d_h2 = (float*)sym(g_h2);
    dim3 g2((N_NODES + BM2 - 1) / BM2, 256 / BN2);
    k_gemm2<<<g2, 256>>>(d_o1, W2, d_h2, N_NODES);
    k_al2<<<(N_NODES * 32 + 255) / 256, 256>>>(a_src2, a_dst2);
    k_gat2<<<(N_NODES + 7) / 8, 256>>>(b2, batch);

    // MLP
    k_mlp1<<<N_GRAPHS * 4, 256>>>(fc1_w, fc1_b);
    k_mlp2<<<N_GRAPHS, 128>>>(fc2_w, fc2_b, out);
}

// round 5
// speedup vs baseline: 4.0311x; 1.1068x over previous
#include <cuda_runtime.h>
#include <cuda_bf16.h>

#define N_NODES 50000
#define N_EDGES 800000
#define NT      850000      // edges + self loops
#define N_GRAPHS 256
#define F_IN    41
#define C1      256
#define C2      256
#define NEG_SLOPE 0.2f

// ---------------- scratch (device globals) ----------------
__device__ __align__(16) float g_h1[N_NODES * C1];
__device__ float g_al_s1[N_NODES * 2];
__device__ float g_al_d1[N_NODES * 2];
__device__ __align__(16) float g_out1[N_NODES * C1];
__device__ __align__(16) float g_h2[N_NODES * C2];
__device__ float g_al_s2[N_NODES];
__device__ float g_al_d2[N_NODES];
__device__ __align__(16) float g_pool[N_GRAPHS * 256];
__device__ float g_cnt[N_GRAPHS];
__device__ float g_fc1[N_GRAPHS * 1024];
// CSR
__device__ int g_deg[N_NODES];
__device__ int g_rowstart[N_NODES + 1];
__device__ int g_cursor[N_NODES];
__device__ int g_csrc[NT];

__device__ __forceinline__ void red_add_v4(float* addr, float4 v) {
    asm volatile("red.global.add.v4.f32 [%0], {%1, %2, %3, %4};"
                 :: "l"(addr), "f"(v.x), "f"(v.y), "f"(v.z), "f"(v.w)
                 : "memory");
}
__device__ __forceinline__ float lrelu(float e) { return e > 0.f ? e : NEG_SLOPE * e; }

// ---------------- CSR build ----------------
__global__ void k_deg(const int* __restrict__ dst) {
    int i = blockIdx.x * blockDim.x + threadIdx.x;
    if (i >= NT) return;
    int d = (i < N_EDGES) ? dst[i] : i - N_EDGES;
    atomicAdd(&g_deg[d], 1);
}

// single-block exclusive scan over g_deg -> g_rowstart, g_cursor
__global__ void k_scan() {
    __shared__ int warp_sums[32];
    __shared__ int s_carry;
    int tid = threadIdx.x, lane = tid & 31, w = tid >> 5;
    if (tid == 0) s_carry = 0;
    __syncthreads();
    for (int base = 0; base < N_NODES; base += 1024) {
        int i = base + tid;
        int v = (i < N_NODES) ? g_deg[i] : 0;
        int incl = v;
#pragma unroll
        for (int o = 1; o < 32; o <<= 1) {
            int t = __shfl_up_sync(0xFFFFFFFFu, incl, o);
            if (lane >= o) incl += t;
        }
        if (lane == 31) warp_sums[w] = incl;
        __syncthreads();
        if (w == 0) {
            int s = warp_sums[lane];
#pragma unroll
            for (int o = 1; o < 32; o <<= 1) {
                int t = __shfl_up_sync(0xFFFFFFFFu, s, o);
                if (lane >= o) s += t;
            }
            warp_sums[lane] = s;    // inclusive over warps
        }
        __syncthreads();
        int warp_off = (w == 0) ? 0 : warp_sums[w - 1];
        int excl = s_carry + warp_off + incl - v;
        if (i < N_NODES) { g_rowstart[i] = excl; g_cursor[i] = excl; }
        __syncthreads();
        if (tid == 0) s_carry += warp_sums[31];
        __syncthreads();
    }
    if (tid == 0) g_rowstart[N_NODES] = NT;
}

__global__ void k_fill(const int* __restrict__ src, const int* __restrict__ dst) {
    int i = blockIdx.x * blockDim.x + threadIdx.x;
    if (i >= NT) return;
    int s, d;
    if (i < N_EDGES) { s = src[i]; d = dst[i]; } else { s = d = i - N_EDGES; }
    int p = atomicAdd(&g_cursor[d], 1);
    g_csrc[p] = s;
}

// ---------------- layer 1 tiled GEMM + attention logits (fused) ----------------
// 32 nodes per 256-thread block. W1 staged once in smem. Thread (tr,tc) computes
// nodes {tr*2, tr*2+1} x 16 strided columns {tc + 16*i}. Head split: i<8 -> h0.
#define G1_M 32
__global__ void __launch_bounds__(256) k_gemm1(const float* __restrict__ x,
                                               const float* __restrict__ W1,
                                               const float* __restrict__ a_s,
                                               const float* __restrict__ a_d) {
    __shared__ __align__(16) float W1s[F_IN * C1];   // 41*256*4 = 41984 B
    __shared__ float xs[G1_M][43];                   // pad 43 -> conflict-free
    int tid = threadIdx.x;
    int n0 = blockIdx.x * G1_M;

    for (int idx = tid; idx < (F_IN * C1) / 4; idx += 256)
        ((float4*)W1s)[idx] = ((const float4*)W1)[idx];
    for (int idx = tid; idx < G1_M * F_IN; idx += 256) {
        int r = idx / F_IN, c = idx % F_IN;
        int node = n0 + r;
        xs[r][c] = (node < N_NODES) ? x[node * F_IN + c] : 0.f;
    }
    __syncthreads();

    int tr = tid >> 4, tc = tid & 15;
    int r0 = tr * 2, r1 = r0 + 1;
    float acc0[16], acc1[16];
#pragma unroll
    for (int i = 0; i < 16; i++) { acc0[i] = 0.f; acc1[i] = 0.f; }

#pragma unroll 1
    for (int k = 0; k < F_IN; k++) {
        float a0 = xs[r0][k], a1 = xs[r1][k];
        const float* wrow = &W1s[k * C1];
#pragma unroll
        for (int i = 0; i < 16; i++) {
            float b = wrow[tc + 16 * i];
            acc0[i] += a0 * b;
            acc1[i] += a1 * b;
        }
    }

    int node0 = n0 + r0, node1 = n0 + r1;
    // store h1 + per-thread partial logits (a_s/a_d flat layout matches col index)
    float s0h0 = 0.f, s0h1 = 0.f, d0h0 = 0.f, d0h1 = 0.f;
    float s1h0 = 0.f, s1h1 = 0.f, d1h0 = 0.f, d1h1 = 0.f;
#pragma unroll
    for (int i = 0; i < 16; i++) {
        int c = tc + 16 * i;
        float as = a_s[c], ad = a_d[c];
        if (i < 8) { s0h0 += acc0[i] * as; d0h0 += acc0[i] * ad;
                     s1h0 += acc1[i] * as; d1h0 += acc1[i] * ad; }
        else       { s0h1 += acc0[i] * as; d0h1 += acc0[i] * ad;
                     s1h1 += acc1[i] * as; d1h1 += acc1[i] * ad; }
        if (node0 < N_NODES) g_h1[node0 * C1 + c] = acc0[i];
        if (node1 < N_NODES) g_h1[node1 * C1 + c] = acc1[i];
    }
    // reduce across the 16 tc lanes (stay inside the 16-lane half-warp group)
#pragma unroll
    for (int o = 8; o > 0; o >>= 1) {
        s0h0 += __shfl_xor_sync(0xFFFFFFFFu, s0h0, o);
        s0h1 += __shfl_xor_sync(0xFFFFFFFFu, s0h1, o);
        d0h0 += __shfl_xor_sync(0xFFFFFFFFu, d0h0, o);
        d0h1 += __shfl_xor_sync(0xFFFFFFFFu, d0h1, o);
        s1h0 += __shfl_xor_sync(0xFFFFFFFFu, s1h0, o);
        s1h1 += __shfl_xor_sync(0xFFFFFFFFu, s1h1, o);
        d1h0 += __shfl_xor_sync(0xFFFFFFFFu, d1h0, o);
        d1h1 += __shfl_xor_sync(0xFFFFFFFFu, d1h1, o);
    }
    if (tc == 0) {
        if (node0 < N_NODES) {
            g_al_s1[node0 * 2]     = s0h0;  g_al_s1[node0 * 2 + 1] = s0h1;
            g_al_d1[node0 * 2]     = d0h0;  g_al_d1[node0 * 2 + 1] = d0h1;
        }
        if (node1 < N_NODES) {
            g_al_s1[node1 * 2]     = s1h0;  g_al_s1[node1 * 2 + 1] = s1h1;
            g_al_d1[node1 * 2]     = d1h0;  g_al_d1[node1 * 2 + 1] = d1h1;
        }
    }
}

// ---------------- layer 1 fused softmax+gather, warp per dst node ----------------
__global__ void k_gat1(const float* __restrict__ b1) {
    int n = blockIdx.x * 8 + (threadIdx.x >> 5);
    int lane = threadIdx.x & 31;
    if (n >= N_NODES) return;
    int row = g_rowstart[n], end = g_rowstart[n + 1];
    float alD0 = g_al_d1[n * 2], alD1 = g_al_d1[n * 2 + 1];

    // pass1: max logit per head
    float m0 = -1e30f, m1 = -1e30f;
    for (int j = row + lane; j < end; j += 32) {
        int s = __ldg(&g_csrc[j]);
        m0 = fmaxf(m0, lrelu(__ldg(&g_al_s1[s * 2]) + alD0));
        m1 = fmaxf(m1, lrelu(__ldg(&g_al_s1[s * 2 + 1]) + alD1));
    }
#pragma unroll
    for (int o = 16; o > 0; o >>= 1) {
        m0 = fmaxf(m0, __shfl_xor_sync(0xFFFFFFFFu, m0, o));
        m1 = fmaxf(m1, __shfl_xor_sync(0xFFFFFFFFu, m1, o));
    }
    int h = lane >> 4;                 // this lane's channels' head
    float mh = h ? m1 : m0;
    float alDh = h ? alD1 : alD0;

    // pass2: exp weights + gather-accumulate (channels lane*8 .. lane*8+7)
    float den = 0.f;
    float acc[8] = {0.f, 0.f, 0.f, 0.f, 0.f, 0.f, 0.f, 0.f};
    for (int j0 = row; j0 < end; j0 += 32) {
        int sj = (j0 + lane < end) ? __ldg(&g_csrc[j0 + lane]) : 0;
        int cnt = min(32, end - j0);
        for (int k = 0; k < cnt; k++) {
            int s = __shfl_sync(0xFFFFFFFFu, sj, k);
            float e = lrelu(__ldg(&g_al_s1[s * 2 + h]) + alDh);
            float wgt = __expf(e - mh);
            den += wgt;
            const float4* hp = (const float4*)&g_h1[s * C1 + lane * 8];
            float4 v0 = hp[0], v1 = hp[1];
            acc[0] += wgt * v0.x; acc[1] += wgt * v0.y;
            acc[2] += wgt * v0.z; acc[3] += wgt * v0.w;
            acc[4] += wgt * v1.x; acc[5] += wgt * v1.y;
            acc[6] += wgt * v1.z; acc[7] += wgt * v1.w;
        }
    }
    float inv = 1.f / (den + 1e-16f);
    int c0 = lane * 8;
    float4 o0, o1;
    o0.x = fmaxf(acc[0] * inv + b1[c0 + 0], 0.f);
    o0.y = fmaxf(acc[1] * inv + b1[c0 + 1], 0.f);
    o0.z = fmaxf(acc[2] * inv + b1[c0 + 2], 0.f);
    o0.w = fmaxf(acc[3] * inv + b1[c0 + 3], 0.f);
    o1.x = fmaxf(acc[4] * inv + b1[c0 + 4], 0.f);
    o1.y = fmaxf(acc[5] * inv + b1[c0 + 5], 0.f);
    o1.z = fmaxf(acc[6] * inv + b1[c0 + 6], 0.f);
    o1.w = fmaxf(acc[7] * inv + b1[c0 + 7], 0.f);
    *(float4*)&g_out1[n * C1 + c0] = o0;
    *(float4*)&g_out1[n * C1 + c0 + 4] = o1;
}

// ---------------- SGEMM 128x128x16, 8x8 per thread: g_h2 = g_out1 @ W2 ----------------
#define BM2 128
#define BN2 128
#define BK2 16
__global__ void __launch_bounds__(256) k_gemm2(const float* __restrict__ A,
                                               const float* __restrict__ B,
                                               float* __restrict__ C, int M) {
    __shared__ __align__(16) float As[BK2][BM2];
    __shared__ __align__(16) float Bs[BK2][BN2];
    int bm = blockIdx.x * BM2, bn = blockIdx.y * BN2;
    int tid = threadIdx.x;
    int tr = tid >> 4, tc = tid & 15;
    float acc[8][8] = {};
    int ar = tid >> 2, ac = (tid & 3) * 4;
    int br = tid >> 5, bc = (tid & 31) * 4;
    for (int k0 = 0; k0 < 256; k0 += BK2) {
#pragma unroll
        for (int half = 0; half < 2; half++) {
            int r = ar + half * 64;
            float4 av = (bm + r < M) ? *(const float4*)&A[(size_t)(bm + r) * 256 + k0 + ac]
                                     : make_float4(0.f, 0.f, 0.f, 0.f);
            As[ac + 0][r] = av.x; As[ac + 1][r] = av.y;
            As[ac + 2][r] = av.z; As[ac + 3][r] = av.w;
        }
#pragma unroll
        for (int half = 0; half < 2; half++) {
            int r = br + half * 8;
            *(float4*)&Bs[r][bc] = *(const float4*)&B[(size_t)(k0 + r) * 256 + bn + bc];
        }
        __syncthreads();
#pragma unroll
        for (int kk = 0; kk < BK2; kk++) {
            float a[8], b[8];
#pragma unroll
            for (int i = 0; i < 8; i++) a[i] = As[kk][tr * 8 + i];
#pragma unroll
            for (int j = 0; j < 8; j++) b[j] = Bs[kk][tc * 8 + j];
#pragma unroll
            for (int i = 0; i < 8; i++)
#pragma unroll
                for (int j = 0; j < 8; j++) acc[i][j] += a[i] * b[j];
        }
        __syncthreads();
    }
#pragma unroll
    for (int i = 0; i < 8; i++) {
        int r = bm + tr * 8 + i;
        if (r < M) {
            *(float4*)&C[(size_t)r * 256 + bn + tc * 8]     =
                make_float4(acc[i][0], acc[i][1], acc[i][2], acc[i][3]);
            *(float4*)&C[(size_t)r * 256 + bn + tc * 8 + 4] =
                make_float4(acc[i][4], acc[i][5], acc[i][6], acc[i][7]);
        }
    }
}

// ---------------- layer 2 attention logits, warp per node ----------------
__global__ void k_al2(const float* __restrict__ as2, const float* __restrict__ ad2) {
    int gidx = blockIdx.x * blockDim.x + threadIdx.x;
    int n = gidx >> 5;
    int lane = gidx & 31;
    if (n >= N_NODES) return;
    float vs = 0.f, vd = 0.f;
#pragma unroll
    for (int c = lane; c < 256; c += 32) {
        float hv = g_h2[n * 256 + c];
        vs += hv * as2[c];
        vd += hv * ad2[c];
    }
#pragma unroll
    for (int o = 16; o > 0; o >>= 1) {
        vs += __shfl_down_sync(0xFFFFFFFFu, vs, o);
        vd += __shfl_down_sync(0xFFFFFFFFu, vd, o);
    }
    if (lane == 0) { g_al_s2[n] = vs; g_al_d2[n] = vd; }
}

// ---------------- layer 2 fused softmax+gather + bias/relu + pool, warp per dst ----------------
__global__ void k_gat2(const float* __restrict__ b2, const int* __restrict__ batch) {
    int n = blockIdx.x * 8 + (threadIdx.x >> 5);
    int lane = threadIdx.x & 31;
    if (n >= N_NODES) return;
    int row = g_rowstart[n], end = g_rowstart[n + 1];
    float alD = g_al_d2[n];

    float m = -1e30f;
    for (int j = row + lane; j < end; j += 32) {
        int s = __ldg(&g_csrc[j]);
        m = fmaxf(m, lrelu(__ldg(&g_al_s2[s]) + alD));
    }
#pragma unroll
    for (int o = 16; o > 0; o >>= 1)
        m = fmaxf(m, __shfl_xor_sync(0xFFFFFFFFu, m, o));

    float den = 0.f;
    float acc[8] = {0.f, 0.f, 0.f, 0.f, 0.f, 0.f, 0.f, 0.f};
    for (int j0 = row; j0 < end; j0 += 32) {
        int sj = (j0 + lane < end) ? __ldg(&g_csrc[j0 + lane]) : 0;
        int cnt = min(32, end - j0);
        for (int k = 0; k < cnt; k++) {
            int s = __shfl_sync(0xFFFFFFFFu, sj, k);
            float e = lrelu(__ldg(&g_al_s2[s]) + alD);
            float wgt = __expf(e - m);
            den += wgt;
            const float4* hp = (const float4*)&g_h2[s * C2 + lane * 8];
            float4 v0 = hp[0], v1 = hp[1];
            acc[0] += wgt * v0.x; acc[1] += wgt * v0.y;
            acc[2] += wgt * v0.z; acc[3] += wgt * v0.w;
            acc[4] += wgt * v1.x; acc[5] += wgt * v1.y;
            acc[6] += wgt * v1.z; acc[7] += wgt * v1.w;
        }
    }
    float inv = 1.f / (den + 1e-16f);
    int c0 = lane * 8;
    float4 o0, o1;
    o0.x = fmaxf(acc[0] * inv + b2[c0 + 0], 0.f);
    o0.y = fmaxf(acc[1] * inv + b2[c0 + 1], 0.f);
    o0.z = fmaxf(acc[2] * inv + b2[c0 + 2], 0.f);
    o0.w = fmaxf(acc[3] * inv + b2[c0 + 3], 0.f);
    o1.x = fmaxf(acc[4] * inv + b2[c0 + 4], 0.f);
    o1.y = fmaxf(acc[5] * inv + b2[c0 + 5], 0.f);
    o1.z = fmaxf(acc[6] * inv + b2[c0 + 6], 0.f);
    o1.w = fmaxf(acc[7] * inv + b2[c0 + 7], 0.f);
    int g = batch[n];
    red_add_v4(&g_pool[g * 256 + c0], o0);
    red_add_v4(&g_pool[g * 256 + c0 + 4], o1);
    if (lane == 0) atomicAdd(&g_cnt[g], 1.0f);
}

// ---------------- MLP head ----------------
__global__ void k_mlp1(const float* __restrict__ fw, const float* __restrict__ fb) {
    int g = blockIdx.x >> 2, q = blockIdx.x & 3;
    int t = threadIdx.x;
    __shared__ float grow[256];
    float inv = 1.0f / fmaxf(g_cnt[g], 1.0f);
    grow[t] = g_pool[g * 256 + t] * inv;
    __syncthreads();
    int col = q * 256 + t;
    float acc = fb[col];
#pragma unroll 8
    for (int k = 0; k < 256; k++) acc += grow[k] * fw[k * 1024 + col];
    g_fc1[g * 1024 + col] = fmaxf(acc, 0.f);
}

__global__ void k_mlp2(const float* __restrict__ fw, const float* __restrict__ fb,
                       float* __restrict__ out) {
    int g = blockIdx.x;
    int t = threadIdx.x; // 128
    __shared__ float row[1024];
    for (int k = t; k < 1024; k += 128) row[k] = g_fc1[g * 1024 + k];
    __syncthreads();
    float acc = fb[t];
#pragma unroll 8
    for (int k = 0; k < 1024; k++) acc += row[k] * fw[k * 128 + t];
    out[g * 128 + t] = acc;
}

// ---------------- host launcher ----------------
static void* sym(const void* s) {
    void* p = nullptr;
    cudaGetSymbolAddress(&p, s);
    return p;
}

extern "C" void kernel_launch(void* const* d_in, const int* in_sizes, int n_in,
                              void* d_out, int out_size) {
    const float* x      = (const float*)d_in[0];
    const int*   src    = (const int*)d_in[1];
    const int*   dst    = (const int*)d_in[2];
    const int*   batch  = (const int*)d_in[3];
    const float* W1     = (const float*)d_in[4];
    const float* a_src1 = (const float*)d_in[5];
    const float* a_dst1 = (const float*)d_in[6];
    const float* b1     = (const float*)d_in[7];
    const float* W2     = (const float*)d_in[8];
    const float* a_src2 = (const float*)d_in[9];
    const float* a_dst2 = (const float*)d_in[10];
    const float* b2     = (const float*)d_in[11];
    const float* fc1_w  = (const float*)d_in[12];
    const float* fc1_b  = (const float*)d_in[13];
    const float* fc2_w  = (const float*)d_in[14];
    const float* fc2_b  = (const float*)d_in[15];
    float* out = (float*)d_out;

    cudaMemsetAsync(sym(g_deg),  0, N_NODES * sizeof(int));
    cudaMemsetAsync(sym(g_pool), 0, N_GRAPHS * 256 * sizeof(float));
    cudaMemsetAsync(sym(g_cnt),  0, N_GRAPHS * sizeof(float));

    // CSR build
    k_deg<<<(NT + 255) / 256, 256>>>(dst);
    k_scan<<<1, 1024>>>();
    k_fill<<<(NT + 255) / 256, 256>>>(src, dst);

    // layer 1
    k_gemm1<<<(N_NODES + G1_M - 1) / G1_M, 256>>>(x, W1, a_src1, a_dst1);
    k_gat1<<<(N_NODES + 7) / 8, 256>>>(b1);

    // layer 2
    float* d_o1 = (float*)sym(g_out1);
    float* d_h2 = (float*)sym(g_h2);
    dim3 g2((N_NODES + BM2 - 1) / BM2, 256 / BN2);
    k_gemm2<<<g2, 256>>>(d_o1, W2, d_h2, N_NODES);
    k_al2<<<(N_NODES * 32 + 255) / 256, 256>>>(a_src2, a_dst2);
    k_gat2<<<(N_NODES + 7) / 8, 256>>>(b2, batch);

    // MLP
    k_mlp1<<<N_GRAPHS * 4, 256>>>(fc1_w, fc1_b);
    k_mlp2<<<N_GRAPHS, 128>>>(fc2_w, fc2_b, out);
}

// round 6
// speedup vs baseline: 4.0370x; 1.0014x over previous
#include <cuda_runtime.h>
#include <cuda_bf16.h>

#define N_NODES 50000
#define N_EDGES 800000
#define NT      850000      // edges + self loops
#define N_GRAPHS 256
#define F_IN    41
#define C1      256
#define C2      256
#define NEG_SLOPE 0.2f

// ---------------- scratch (device globals) ----------------
__device__ __align__(16) float g_h1[N_NODES * C1];
__device__ float g_al_s1[N_NODES * 2];
__device__ float g_al_d1[N_NODES * 2];
__device__ __align__(16) float g_out1[N_NODES * C1];
__device__ __align__(16) float g_h2[N_NODES * C2];
__device__ float g_al_s2[N_NODES];
__device__ float g_al_d2[N_NODES];
__device__ __align__(16) float g_wvs[C2];
__device__ __align__(16) float g_wvd[C2];
__device__ __align__(16) float g_pool[N_GRAPHS * 256];
__device__ float g_cnt[N_GRAPHS];
__device__ float g_fc1[N_GRAPHS * 1024];
// CSR
__device__ int g_deg[N_NODES];
__device__ int g_rowstart[N_NODES + 1];
__device__ int g_cursor[N_NODES];
__device__ int g_csrc[NT];

__device__ __forceinline__ void red_add_v4(float* addr, float4 v) {
    asm volatile("red.global.add.v4.f32 [%0], {%1, %2, %3, %4};"
                 :: "l"(addr), "f"(v.x), "f"(v.y), "f"(v.z), "f"(v.w)
                 : "memory");
}
__device__ __forceinline__ float lrelu(float e) { return e > 0.f ? e : NEG_SLOPE * e; }

// ---------------- CSR build ----------------
__global__ void k_deg(const int* __restrict__ dst) {
    int i = blockIdx.x * blockDim.x + threadIdx.x;
    if (i >= NT) return;
    int d = (i < N_EDGES) ? dst[i] : i - N_EDGES;
    atomicAdd(&g_deg[d], 1);
}

// single-block exclusive scan over g_deg -> g_rowstart, g_cursor
__global__ void k_scan() {
    __shared__ int warp_sums[32];
    __shared__ int s_carry;
    int tid = threadIdx.x, lane = tid & 31, w = tid >> 5;
    if (tid == 0) s_carry = 0;
    __syncthreads();
    for (int base = 0; base < N_NODES; base += 1024) {
        int i = base + tid;
        int v = (i < N_NODES) ? g_deg[i] : 0;
        int incl = v;
#pragma unroll
        for (int o = 1; o < 32; o <<= 1) {
            int t = __shfl_up_sync(0xFFFFFFFFu, incl, o);
            if (lane >= o) incl += t;
        }
        if (lane == 31) warp_sums[w] = incl;
        __syncthreads();
        if (w == 0) {
            int s = warp_sums[lane];
#pragma unroll
            for (int o = 1; o < 32; o <<= 1) {
                int t = __shfl_up_sync(0xFFFFFFFFu, s, o);
                if (lane >= o) s += t;
            }
            warp_sums[lane] = s;    // inclusive over warps
        }
        __syncthreads();
        int warp_off = (w == 0) ? 0 : warp_sums[w - 1];
        int excl = s_carry + warp_off + incl - v;
        if (i < N_NODES) { g_rowstart[i] = excl; g_cursor[i] = excl; }
        __syncthreads();
        if (tid == 0) s_carry += warp_sums[31];
        __syncthreads();
    }
    if (tid == 0) g_rowstart[N_NODES] = NT;
}

__global__ void k_fill(const int* __restrict__ src, const int* __restrict__ dst) {
    int i = blockIdx.x * blockDim.x + threadIdx.x;
    if (i >= NT) return;
    int s, d;
    if (i < N_EDGES) { s = src[i]; d = dst[i]; } else { s = d = i - N_EDGES; }
    int p = atomicAdd(&g_cursor[d], 1);
    g_csrc[p] = s;
}

// ---------------- precompute w_s = W2 @ as2, w_d = W2 @ ad2 ----------------
__global__ void k_wvec(const float* __restrict__ W2, const float* __restrict__ as2,
                       const float* __restrict__ ad2) {
    int k = blockIdx.x * 8 + (threadIdx.x >> 5);
    int lane = threadIdx.x & 31;
    float s = 0.f, d = 0.f;
#pragma unroll
    for (int j = lane; j < 256; j += 32) {
        float w = W2[k * 256 + j];
        s += w * as2[j];
        d += w * ad2[j];
    }
#pragma unroll
    for (int o = 16; o > 0; o >>= 1) {
        s += __shfl_xor_sync(0xFFFFFFFFu, s, o);
        d += __shfl_xor_sync(0xFFFFFFFFu, d, o);
    }
    if (lane == 0) { g_wvs[k] = s; g_wvd[k] = d; }
}

// ---------------- layer 1 tiled GEMM + attention logits (fused) ----------------
// 64 nodes per 256-thread block; thread (tr,tc): rows tr*4..+3 x cols {tc+16i}.
#define G1_M 64
#define G1_SMEM (F_IN * C1 * 4 + G1_M * 43 * 4)
__global__ void __launch_bounds__(256) k_gemm1(const float* __restrict__ x,
                                               const float* __restrict__ W1,
                                               const float* __restrict__ a_s,
                                               const float* __restrict__ a_d) {
    extern __shared__ float sm[];
    float* W1s = sm;                                  // F_IN*C1
    float (*xs)[43] = (float (*)[43])(sm + F_IN * C1);
    int tid = threadIdx.x;
    int n0 = blockIdx.x * G1_M;

    for (int idx = tid; idx < (F_IN * C1) / 4; idx += 256)
        ((float4*)W1s)[idx] = ((const float4*)W1)[idx];
    for (int idx = tid; idx < G1_M * F_IN; idx += 256) {
        int r = idx / F_IN, c = idx % F_IN;
        int node = n0 + r;
        xs[r][c] = (node < N_NODES) ? x[node * F_IN + c] : 0.f;
    }
    __syncthreads();

    int tr = tid >> 4, tc = tid & 15;
    float acc[4][16];
#pragma unroll
    for (int j = 0; j < 4; j++)
#pragma unroll
        for (int i = 0; i < 16; i++) acc[j][i] = 0.f;

#pragma unroll 1
    for (int k = 0; k < F_IN; k++) {
        float a0 = xs[tr * 4 + 0][k];
        float a1 = xs[tr * 4 + 1][k];
        float a2 = xs[tr * 4 + 2][k];
        float a3 = xs[tr * 4 + 3][k];
        const float* wrow = &W1s[k * C1];
#pragma unroll
        for (int i = 0; i < 16; i++) {
            float b = wrow[tc + 16 * i];
            acc[0][i] += a0 * b;
            acc[1][i] += a1 * b;
            acc[2][i] += a2 * b;
            acc[3][i] += a3 * b;
        }
    }

    // store h1 + per-thread partial logits
    float sh0[4], sh1[4], dh0[4], dh1[4];
#pragma unroll
    for (int j = 0; j < 4; j++) { sh0[j] = sh1[j] = dh0[j] = dh1[j] = 0.f; }
#pragma unroll
    for (int i = 0; i < 16; i++) {
        int c = tc + 16 * i;
        float as = a_s[c], ad = a_d[c];
#pragma unroll
        for (int j = 0; j < 4; j++) {
            if (i < 8) { sh0[j] += acc[j][i] * as; dh0[j] += acc[j][i] * ad; }
            else       { sh1[j] += acc[j][i] * as; dh1[j] += acc[j][i] * ad; }
        }
    }
#pragma unroll
    for (int j = 0; j < 4; j++) {
        int node = n0 + tr * 4 + j;
        if (node < N_NODES) {
#pragma unroll
            for (int i = 0; i < 16; i++) g_h1[node * C1 + tc + 16 * i] = acc[j][i];
        }
    }
    // reduce across 16 tc lanes (xor <= 8 stays inside each 16-lane group)
#pragma unroll
    for (int o = 8; o > 0; o >>= 1) {
#pragma unroll
        for (int j = 0; j < 4; j++) {
            sh0[j] += __shfl_xor_sync(0xFFFFFFFFu, sh0[j], o);
            sh1[j] += __shfl_xor_sync(0xFFFFFFFFu, sh1[j], o);
            dh0[j] += __shfl_xor_sync(0xFFFFFFFFu, dh0[j], o);
            dh1[j] += __shfl_xor_sync(0xFFFFFFFFu, dh1[j], o);
        }
    }
    if (tc == 0) {
#pragma unroll
        for (int j = 0; j < 4; j++) {
            int node = n0 + tr * 4 + j;
            if (node < N_NODES) {
                g_al_s1[node * 2]     = sh0[j];  g_al_s1[node * 2 + 1] = sh1[j];
                g_al_d1[node * 2]     = dh0[j];  g_al_d1[node * 2 + 1] = dh1[j];
            }
        }
    }
}

// ---------------- layer 1 fused softmax+gather (no max pass) + al2 epilogue ----------------
__global__ void k_gat1(const float* __restrict__ b1) {
    int n = blockIdx.x * 8 + (threadIdx.x >> 5);
    int lane = threadIdx.x & 31;
    if (n >= N_NODES) return;
    int row = g_rowstart[n], end = g_rowstart[n + 1];
    int h = lane >> 4;                 // this lane's channels' head
    float alDh = g_al_d1[n * 2 + h];

    // single pass: exp weights + gather-accumulate (channels lane*8 .. lane*8+7)
    float den = 0.f;
    float acc[8] = {0.f, 0.f, 0.f, 0.f, 0.f, 0.f, 0.f, 0.f};
    for (int j0 = row; j0 < end; j0 += 32) {
        int sj = (j0 + lane < end) ? __ldg(&g_csrc[j0 + lane]) : 0;
        int cnt = min(32, end - j0);
        for (int k = 0; k < cnt; k++) {
            int s = __shfl_sync(0xFFFFFFFFu, sj, k);
            float e = lrelu(__ldg(&g_al_s1[s * 2 + h]) + alDh);
            float wgt = __expf(e);               // logits bounded, no max needed
            den += wgt;
            const float4* hp = (const float4*)&g_h1[s * C1 + lane * 8];
            float4 v0 = hp[0], v1 = hp[1];
            acc[0] += wgt * v0.x; acc[1] += wgt * v0.y;
            acc[2] += wgt * v0.z; acc[3] += wgt * v0.w;
            acc[4] += wgt * v1.x; acc[5] += wgt * v1.y;
            acc[6] += wgt * v1.z; acc[7] += wgt * v1.w;
        }
    }
    float inv = 1.f / (den + 1e-16f);
    int c0 = lane * 8;
    float4 o0, o1;
    o0.x = fmaxf(acc[0] * inv + b1[c0 + 0], 0.f);
    o0.y = fmaxf(acc[1] * inv + b1[c0 + 1], 0.f);
    o0.z = fmaxf(acc[2] * inv + b1[c0 + 2], 0.f);
    o0.w = fmaxf(acc[3] * inv + b1[c0 + 3], 0.f);
    o1.x = fmaxf(acc[4] * inv + b1[c0 + 4], 0.f);
    o1.y = fmaxf(acc[5] * inv + b1[c0 + 5], 0.f);
    o1.z = fmaxf(acc[6] * inv + b1[c0 + 6], 0.f);
    o1.w = fmaxf(acc[7] * inv + b1[c0 + 7], 0.f);
    *(float4*)&g_out1[n * C1 + c0] = o0;
    *(float4*)&g_out1[n * C1 + c0 + 4] = o1;

    // fused al2: al_s2[n] = relu(out1[n]) . (W2 @ as2)  (likewise d)
    float4 ws0 = *(const float4*)&g_wvs[c0], ws1 = *(const float4*)&g_wvs[c0 + 4];
    float4 wd0 = *(const float4*)&g_wvd[c0], wd1 = *(const float4*)&g_wvd[c0 + 4];
    float ps = o0.x * ws0.x + o0.y * ws0.y + o0.z * ws0.z + o0.w * ws0.w
             + o1.x * ws1.x + o1.y * ws1.y + o1.z * ws1.z + o1.w * ws1.w;
    float pd = o0.x * wd0.x + o0.y * wd0.y + o0.z * wd0.z + o0.w * wd0.w
             + o1.x * wd1.x + o1.y * wd1.y + o1.z * wd1.z + o1.w * wd1.w;
#pragma unroll
    for (int o = 16; o > 0; o >>= 1) {
        ps += __shfl_xor_sync(0xFFFFFFFFu, ps, o);
        pd += __shfl_xor_sync(0xFFFFFFFFu, pd, o);
    }
    if (lane == 0) { g_al_s2[n] = ps; g_al_d2[n] = pd; }
}

// ---------------- SGEMM 128x128x16, 8x8 per thread: g_h2 = g_out1 @ W2 ----------------
#define BM2 128
#define BN2 128
#define BK2 16
__global__ void __launch_bounds__(256) k_gemm2(const float* __restrict__ A,
                                               const float* __restrict__ B,
                                               float* __restrict__ C, int M) {
    __shared__ __align__(16) float As[BK2][BM2];
    __shared__ __align__(16) float Bs[BK2][BN2];
    int bm = blockIdx.x * BM2, bn = blockIdx.y * BN2;
    int tid = threadIdx.x;
    int tr = tid >> 4, tc = tid & 15;
    float acc[8][8] = {};
    int ar = tid >> 2, ac = (tid & 3) * 4;
    int br = tid >> 5, bc = (tid & 31) * 4;
    for (int k0 = 0; k0 < 256; k0 += BK2) {
#pragma unroll
        for (int half = 0; half < 2; half++) {
            int r = ar + half * 64;
            float4 av = (bm + r < M) ? *(const float4*)&A[(size_t)(bm + r) * 256 + k0 + ac]
                                     : make_float4(0.f, 0.f, 0.f, 0.f);
            As[ac + 0][r] = av.x; As[ac + 1][r] = av.y;
            As[ac + 2][r] = av.z; As[ac + 3][r] = av.w;
        }
#pragma unroll
        for (int half = 0; half < 2; half++) {
            int r = br + half * 8;
            *(float4*)&Bs[r][bc] = *(const float4*)&B[(size_t)(k0 + r) * 256 + bn + bc];
        }
        __syncthreads();
#pragma unroll
        for (int kk = 0; kk < BK2; kk++) {
            float a[8], b[8];
#pragma unroll
            for (int i = 0; i < 8; i++) a[i] = As[kk][tr * 8 + i];
#pragma unroll
            for (int j = 0; j < 8; j++) b[j] = Bs[kk][tc * 8 + j];
#pragma unroll
            for (int i = 0; i < 8; i++)
#pragma unroll
                for (int j = 0; j < 8; j++) acc[i][j] += a[i] * b[j];
        }
        __syncthreads();
    }
#pragma unroll
    for (int i = 0; i < 8; i++) {
        int r = bm + tr * 8 + i;
        if (r < M) {
            *(float4*)&C[(size_t)r * 256 + bn + tc * 8]     =
                make_float4(acc[i][0], acc[i][1], acc[i][2], acc[i][3]);
            *(float4*)&C[(size_t)r * 256 + bn + tc * 8 + 4] =
                make_float4(acc[i][4], acc[i][5], acc[i][6], acc[i][7]);
        }
    }
}

// ---------------- layer 2 fused softmax+gather (no max) + bias/relu + pool ----------------
__global__ void k_gat2(const float* __restrict__ b2, const int* __restrict__ batch) {
    int n = blockIdx.x * 8 + (threadIdx.x >> 5);
    int lane = threadIdx.x & 31;
    if (n >= N_NODES) return;
    int row = g_rowstart[n], end = g_rowstart[n + 1];
    float alD = g_al_d2[n];

    float den = 0.f;
    float acc[8] = {0.f, 0.f, 0.f, 0.f, 0.f, 0.f, 0.f, 0.f};
    for (int j0 = row; j0 < end; j0 += 32) {
        int sj = (j0 + lane < end) ? __ldg(&g_csrc[j0 + lane]) : 0;
        int cnt = min(32, end - j0);
        for (int k = 0; k < cnt; k++) {
            int s = __shfl_sync(0xFFFFFFFFu, sj, k);
            float e = lrelu(__ldg(&g_al_s2[s]) + alD);
            float wgt = __expf(e);
            den += wgt;
            const float4* hp = (const float4*)&g_h2[s * C2 + lane * 8];
            float4 v0 = hp[0], v1 = hp[1];
            acc[0] += wgt * v0.x; acc[1] += wgt * v0.y;
            acc[2] += wgt * v0.z; acc[3] += wgt * v0.w;
            acc[4] += wgt * v1.x; acc[5] += wgt * v1.y;
            acc[6] += wgt * v1.z; acc[7] += wgt * v1.w;
        }
    }
    float inv = 1.f / (den + 1e-16f);
    int c0 = lane * 8;
    float4 o0, o1;
    o0.x = fmaxf(acc[0] * inv + b2[c0 + 0], 0.f);
    o0.y = fmaxf(acc[1] * inv + b2[c0 + 1], 0.f);
    o0.z = fmaxf(acc[2] * inv + b2[c0 + 2], 0.f);
    o0.w = fmaxf(acc[3] * inv + b2[c0 + 3], 0.f);
    o1.x = fmaxf(acc[4] * inv + b2[c0 + 4], 0.f);
    o1.y = fmaxf(acc[5] * inv + b2[c0 + 5], 0.f);
    o1.z = fmaxf(acc[6] * inv + b2[c0 + 6], 0.f);
    o1.w = fmaxf(acc[7] * inv + b2[c0 + 7], 0.f);
    int g = batch[n];
    red_add_v4(&g_pool[g * 256 + c0], o0);
    red_add_v4(&g_pool[g * 256 + c0 + 4], o1);
    if (lane == 0) atomicAdd(&g_cnt[g], 1.0f);
}

// ---------------- MLP head ----------------
__global__ void k_mlp1(const float* __restrict__ fw, const float* __restrict__ fb) {
    int g = blockIdx.x >> 2, q = blockIdx.x & 3;
    int t = threadIdx.x;
    __shared__ float grow[256];
    float inv = 1.0f / fmaxf(g_cnt[g], 1.0f);
    grow[t] = g_pool[g * 256 + t] * inv;
    __syncthreads();
    int col = q * 256 + t;
    float acc = fb[col];
#pragma unroll 8
    for (int k = 0; k < 256; k++) acc += grow[k] * fw[k * 1024 + col];
    g_fc1[g * 1024 + col] = fmaxf(acc, 0.f);
}

__global__ void k_mlp2(const float* __restrict__ fw, const float* __restrict__ fb,
                       float* __restrict__ out) {
    int g = blockIdx.x;
    int t = threadIdx.x; // 128
    __shared__ float row[1024];
    for (int k = t; k < 1024; k += 128) row[k] = g_fc1[g * 1024 + k];
    __syncthreads();
    float acc = fb[t];
#pragma unroll 8
    for (int k = 0; k < 1024; k++) acc += row[k] * fw[k * 128 + t];
    out[g * 128 + t] = acc;
}

// ---------------- host launcher ----------------
static void* sym(const void* s) {
    void* p = nullptr;
    cudaGetSymbolAddress(&p, s);
    return p;
}

extern "C" void kernel_launch(void* const* d_in, const int* in_sizes, int n_in,
                              void* d_out, int out_size) {
    const float* x      = (const float*)d_in[0];
    const int*   src    = (const int*)d_in[1];
    const int*   dst    = (const int*)d_in[2];
    const int*   batch  = (const int*)d_in[3];
    const float* W1     = (const float*)d_in[4];
    const float* a_src1 = (const float*)d_in[5];
    const float* a_dst1 = (const float*)d_in[6];
    const float* b1     = (const float*)d_in[7];
    const float* W2     = (const float*)d_in[8];
    const float* a_src2 = (const float*)d_in[9];
    const float* a_dst2 = (const float*)d_in[10];
    const float* b2     = (const float*)d_in[11];
    const float* fc1_w  = (const float*)d_in[12];
    const float* fc1_b  = (const float*)d_in[13];
    const float* fc2_w  = (const float*)d_in[14];
    const float* fc2_b  = (const float*)d_in[15];
    float* out = (float*)d_out;

    static bool attr_set = false;
    if (!attr_set) {
        cudaFuncSetAttribute(k_gemm1, cudaFuncAttributeMaxDynamicSharedMemorySize, G1_SMEM);
        attr_set = true;
    }

    cudaMemsetAsync(sym(g_deg),  0, N_NODES * sizeof(int));
    cudaMemsetAsync(sym(g_pool), 0, N_GRAPHS * 256 * sizeof(float));
    cudaMemsetAsync(sym(g_cnt),  0, N_GRAPHS * sizeof(float));

    // CSR build
    k_deg<<<(NT + 255) / 256, 256>>>(dst);
    k_scan<<<1, 1024>>>();
    k_fill<<<(NT + 255) / 256, 256>>>(src, dst);

    // precompute W2 @ a vectors (independent of everything above)
    k_wvec<<<32, 256>>>(W2, a_src2, a_dst2);

    // layer 1
    k_gemm1<<<(N_NODES + G1_M - 1) / G1_M, 256, G1_SMEM>>>(x, W1, a_src1, a_dst1);
    k_gat1<<<(N_NODES + 7) / 8, 256>>>(b1);

    // layer 2
    float* d_o1 = (float*)sym(g_out1);
    float* d_h2 = (float*)sym(g_h2);
    dim3 g2((N_NODES + BM2 - 1) / BM2, 256 / BN2);
    k_gemm2<<<g2, 256>>>(d_o1, W2, d_h2, N_NODES);
    k_gat2<<<(N_NODES + 7) / 8, 256>>>(b2, batch);

    // MLP
    k_mlp1<<<N_GRAPHS * 4, 256>>>(fc1_w, fc1_b);
    k_mlp2<<<N_GRAPHS, 128>>>(fc2_w, fc2_b, out);
}

// round 8
// speedup vs baseline: 4.2416x; 1.0507x over previous
#include <cuda_runtime.h>
#include <cuda_bf16.h>
#include <mma.h>
using namespace nvcuda;

#define N_NODES 50000
#define N_PAD   50048       // padded to multiple of 128 for the TC GEMM
#define N_EDGES 800000
#define NT      850000      // edges + self loops
#define N_GRAPHS 256
#define F_IN    41
#define C1      256
#define C2      256
#define NEG_SLOPE 0.2f

// ---------------- scratch (device globals) ----------------
__device__ __align__(16) float g_h1[N_NODES * C1];
__device__ float g_al_s1[N_NODES * 2];
__device__ float g_al_d1[N_NODES * 2];
__device__ __align__(16) float g_out1[N_PAD * C1];   // pad rows stay zero
__device__ __align__(16) float g_h2[N_PAD * C2];
__device__ float g_al_s2[N_NODES];
__device__ float g_al_d2[N_NODES];
__device__ __align__(16) float g_wvs[C2];
__device__ __align__(16) float g_wvd[C2];
__device__ __align__(16) float g_pool[N_GRAPHS * 256];
__device__ float g_cnt[N_GRAPHS];
__device__ float g_fc1[N_GRAPHS * 1024];
// CSR
__device__ int g_deg[N_NODES];
__device__ int g_rowstart[N_NODES + 1];
__device__ int g_cursor[N_NODES];
__device__ int g_csrc[NT];

__device__ __forceinline__ void red_add_v4(float* addr, float4 v) {
    asm volatile("red.global.add.v4.f32 [%0], {%1, %2, %3, %4};"
                 :: "l"(addr), "f"(v.x), "f"(v.y), "f"(v.z), "f"(v.w)
                 : "memory");
}
__device__ __forceinline__ float lrelu(float e) { return e > 0.f ? e : NEG_SLOPE * e; }

// ---------------- CSR build ----------------
__global__ void k_deg(const int* __restrict__ dst) {
    int i = blockIdx.x * blockDim.x + threadIdx.x;
    if (i >= NT) return;
    int d = (i < N_EDGES) ? dst[i] : i - N_EDGES;
    atomicAdd(&g_deg[d], 1);
}

// single-block exclusive scan over g_deg -> g_rowstart, g_cursor
__global__ void k_scan() {
    __shared__ int warp_sums[32];
    __shared__ int s_carry;
    int tid = threadIdx.x, lane = tid & 31, w = tid >> 5;
    if (tid == 0) s_carry = 0;
    __syncthreads();
    for (int base = 0; base < N_NODES; base += 1024) {
        int i = base + tid;
        int v = (i < N_NODES) ? g_deg[i] : 0;
        int incl = v;
#pragma unroll
        for (int o = 1; o < 32; o <<= 1) {
            int t = __shfl_up_sync(0xFFFFFFFFu, incl, o);
            if (lane >= o) incl += t;
        }
        if (lane == 31) warp_sums[w] = incl;
        __syncthreads();
        if (w == 0) {
            int s = warp_sums[lane];
#pragma unroll
            for (int o = 1; o < 32; o <<= 1) {
                int t = __shfl_up_sync(0xFFFFFFFFu, s, o);
                if (lane >= o) s += t;
            }
            warp_sums[lane] = s;    // inclusive over warps
        }
        __syncthreads();
        int warp_off = (w == 0) ? 0 : warp_sums[w - 1];
        int excl = s_carry + warp_off + incl - v;
        if (i < N_NODES) { g_rowstart[i] = excl; g_cursor[i] = excl; }
        __syncthreads();
        if (tid == 0) s_carry += warp_sums[31];
        __syncthreads();
    }
    if (tid == 0) g_rowstart[N_NODES] = NT;
}

__global__ void k_fill(const int* __restrict__ src, const int* __restrict__ dst) {
    int i = blockIdx.x * blockDim.x + threadIdx.x;
    if (i >= NT) return;
    int s, d;
    if (i < N_EDGES) { s = src[i]; d = dst[i]; } else { s = d = i - N_EDGES; }
    int p = atomicAdd(&g_cursor[d], 1);
    g_csrc[p] = s;
}

// ---------------- precompute w_s = W2 @ as2, w_d = W2 @ ad2 ----------------
__global__ void k_wvec(const float* __restrict__ W2, const float* __restrict__ as2,
                       const float* __restrict__ ad2) {
    int k = blockIdx.x * 8 + (threadIdx.x >> 5);
    int lane = threadIdx.x & 31;
    float s = 0.f, d = 0.f;
#pragma unroll
    for (int j = lane; j < 256; j += 32) {
        float w = W2[k * 256 + j];
        s += w * as2[j];
        d += w * ad2[j];
    }
#pragma unroll
    for (int o = 16; o > 0; o >>= 1) {
        s += __shfl_xor_sync(0xFFFFFFFFu, s, o);
        d += __shfl_xor_sync(0xFFFFFFFFu, d, o);
    }
    if (lane == 0) { g_wvs[k] = s; g_wvd[k] = d; }
}

// ---------------- layer 1 tiled GEMM + attention logits (fused) ----------------
// 64 nodes per 256-thread block; thread (tr,tc): rows tr*4..+3 x cols {tc+16i}.
#define G1_M 64
#define G1_SMEM (F_IN * C1 * 4 + G1_M * 43 * 4)
__global__ void __launch_bounds__(256) k_gemm1(const float* __restrict__ x,
                                               const float* __restrict__ W1,
                                               const float* __restrict__ a_s,
                                               const float* __restrict__ a_d) {
    extern __shared__ float sm[];
    float* W1s = sm;                                  // F_IN*C1
    float (*xs)[43] = (float (*)[43])(sm + F_IN * C1);
    int tid = threadIdx.x;
    int n0 = blockIdx.x * G1_M;

    for (int idx = tid; idx < (F_IN * C1) / 4; idx += 256)
        ((float4*)W1s)[idx] = ((const float4*)W1)[idx];
    for (int idx = tid; idx < G1_M * F_IN; idx += 256) {
        int r = idx / F_IN, c = idx % F_IN;
        int node = n0 + r;
        xs[r][c] = (node < N_NODES) ? x[node * F_IN + c] : 0.f;
    }
    __syncthreads();

    int tr = tid >> 4, tc = tid & 15;
    float acc[4][16];
#pragma unroll
    for (int j = 0; j < 4; j++)
#pragma unroll
        for (int i = 0; i < 16; i++) acc[j][i] = 0.f;

#pragma unroll 1
    for (int k = 0; k < F_IN; k++) {
        float a0 = xs[tr * 4 + 0][k];
        float a1 = xs[tr * 4 + 1][k];
        float a2 = xs[tr * 4 + 2][k];
        float a3 = xs[tr * 4 + 3][k];
        const float* wrow = &W1s[k * C1];
#pragma unroll
        for (int i = 0; i < 16; i++) {
            float b = wrow[tc + 16 * i];
            acc[0][i] += a0 * b;
            acc[1][i] += a1 * b;
            acc[2][i] += a2 * b;
            acc[3][i] += a3 * b;
        }
    }

    // store h1 + per-thread partial logits
    float sh0[4], sh1[4], dh0[4], dh1[4];
#pragma unroll
    for (int j = 0; j < 4; j++) { sh0[j] = sh1[j] = dh0[j] = dh1[j] = 0.f; }
#pragma unroll
    for (int i = 0; i < 16; i++) {
        int c = tc + 16 * i;
        float as = a_s[c], ad = a_d[c];
#pragma unroll
        for (int j = 0; j < 4; j++) {
            if (i < 8) { sh0[j] += acc[j][i] * as; dh0[j] += acc[j][i] * ad; }
            else       { sh1[j] += acc[j][i] * as; dh1[j] += acc[j][i] * ad; }
        }
    }
#pragma unroll
    for (int j = 0; j < 4; j++) {
        int node = n0 + tr * 4 + j;
        if (node < N_NODES) {
#pragma unroll
            for (int i = 0; i < 16; i++) g_h1[node * C1 + tc + 16 * i] = acc[j][i];
        }
    }
    // reduce across 16 tc lanes (xor <= 8 stays inside each 16-lane group)
#pragma unroll
    for (int o = 8; o > 0; o >>= 1) {
#pragma unroll
        for (int j = 0; j < 4; j++) {
            sh0[j] += __shfl_xor_sync(0xFFFFFFFFu, sh0[j], o);
            sh1[j] += __shfl_xor_sync(0xFFFFFFFFu, sh1[j], o);
            dh0[j] += __shfl_xor_sync(0xFFFFFFFFu, dh0[j], o);
            dh1[j] += __shfl_xor_sync(0xFFFFFFFFu, dh1[j], o);
        }
    }
    if (tc == 0) {
#pragma unroll
        for (int j = 0; j < 4; j++) {
            int node = n0 + tr * 4 + j;
            if (node < N_NODES) {
                g_al_s1[node * 2]     = sh0[j];  g_al_s1[node * 2 + 1] = sh1[j];
                g_al_d1[node * 2]     = dh0[j];  g_al_d1[node * 2 + 1] = dh1[j];
            }
        }
    }
}

// ---------------- layer 1 fused softmax+gather (no max pass) + al2 epilogue ----------------
__global__ void k_gat1(const float* __restrict__ b1) {
    int n = blockIdx.x * 8 + (threadIdx.x >> 5);
    int lane = threadIdx.x & 31;
    if (n >= N_NODES) return;
    int row = g_rowstart[n], end = g_rowstart[n + 1];
    int h = lane >> 4;                 // this lane's channels' head
    float alDh = g_al_d1[n * 2 + h];

    // single pass: exp weights + gather-accumulate (channels lane*8 .. lane*8+7)
    float den = 0.f;
    float acc[8] = {0.f, 0.f, 0.f, 0.f, 0.f, 0.f, 0.f, 0.f};
    for (int j0 = row; j0 < end; j0 += 32) {
        int sj = (j0 + lane < end) ? __ldg(&g_csrc[j0 + lane]) : 0;
        int cnt = min(32, end - j0);
        for (int k = 0; k < cnt; k++) {
            int s = __shfl_sync(0xFFFFFFFFu, sj, k);
            float e = lrelu(__ldg(&g_al_s1[s * 2 + h]) + alDh);
            float wgt = __expf(e);               // logits bounded, no max needed
            den += wgt;
            const float4* hp = (const float4*)&g_h1[s * C1 + lane * 8];
            float4 v0 = hp[0], v1 = hp[1];
            acc[0] += wgt * v0.x; acc[1] += wgt * v0.y;
            acc[2] += wgt * v0.z; acc[3] += wgt * v0.w;
            acc[4] += wgt * v1.x; acc[5] += wgt * v1.y;
            acc[6] += wgt * v1.z; acc[7] += wgt * v1.w;
        }
    }
    float inv = 1.f / (den + 1e-16f);
    int c0 = lane * 8;
    float4 o0, o1;
    o0.x = fmaxf(acc[0] * inv + b1[c0 + 0], 0.f);
    o0.y = fmaxf(acc[1] * inv + b1[c0 + 1], 0.f);
    o0.z = fmaxf(acc[2] * inv + b1[c0 + 2], 0.f);
    o0.w = fmaxf(acc[3] * inv + b1[c0 + 3], 0.f);
    o1.x = fmaxf(acc[4] * inv + b1[c0 + 4], 0.f);
    o1.y = fmaxf(acc[5] * inv + b1[c0 + 5], 0.f);
    o1.z = fmaxf(acc[6] * inv + b1[c0 + 6], 0.f);
    o1.w = fmaxf(acc[7] * inv + b1[c0 + 7], 0.f);
    *(float4*)&g_out1[n * C1 + c0] = o0;
    *(float4*)&g_out1[n * C1 + c0 + 4] = o1;

    // fused al2: al_s2[n] = relu(out1[n]) . (W2 @ as2)  (likewise d)
    float4 ws0 = *(const float4*)&g_wvs[c0], ws1 = *(const float4*)&g_wvs[c0 + 4];
    float4 wd0 = *(const float4*)&g_wvd[c0], wd1 = *(const float4*)&g_wvd[c0 + 4];
    float ps = o0.x * ws0.x + o0.y * ws0.y + o0.z * ws0.z + o0.w * ws0.w
             + o1.x * ws1.x + o1.y * ws1.y + o1.z * ws1.z + o1.w * ws1.w;
    float pd = o0.x * wd0.x + o0.y * wd0.y + o0.z * wd0.z + o0.w * wd0.w
             + o1.x * wd1.x + o1.y * wd1.y + o1.z * wd1.z + o1.w * wd1.w;
#pragma unroll
    for (int o = 16; o > 0; o >>= 1) {
        ps += __shfl_xor_sync(0xFFFFFFFFu, ps, o);
        pd += __shfl_xor_sync(0xFFFFFFFFu, pd, o);
    }
    if (lane == 0) { g_al_s2[n] = ps; g_al_d2[n] = pd; }
}

// ---------------- tf32 tensor-core GEMM: g_h2 = g_out1(N_PAD x 256) @ W2(256 x 256) ----------------
// 128x128 tile per 256-thread block; 8 warps as 4x2 of 32x64 warp tiles.
// Pad rows of g_out1 are zero -> pad rows of g_h2 are zero; no guards needed.
#define TCM 128
#define TCN 128
#define TCK 32
__global__ void __launch_bounds__(256) k_gemm2(const float* __restrict__ A,
                                               const float* __restrict__ B,
                                               float* __restrict__ C) {
    __shared__ __align__(16) float As[TCM][TCK + 4];   // ldm 36 (mult of 4)
    __shared__ __align__(16) float Bs[TCK][TCN + 4];   // ldm 132
    int tid = threadIdx.x;
    int bm = blockIdx.x * TCM, bn = blockIdx.y * TCN;
    int wid = tid >> 5;
    int warp_m = (wid >> 1) * 32, warp_n = (wid & 1) * 64;

    wmma::fragment<wmma::accumulator, 16, 16, 8, float> c_frag[2][4];
#pragma unroll
    for (int i = 0; i < 2; i++)
#pragma unroll
        for (int j = 0; j < 4; j++) wmma::fill_fragment(c_frag[i][j], 0.f);

    for (int k0 = 0; k0 < 256; k0 += TCK) {
        // A tile: 128 rows x 32 cols
#pragma unroll
        for (int p = 0; p < 4; p++) {
            int r = (tid >> 3) + p * 32;
            int c4 = tid & 7;
            float4 v = *(const float4*)&A[(size_t)(bm + r) * 256 + k0 + c4 * 4];
            *(float4*)&As[r][c4 * 4] = v;
        }
        // B tile: 32 rows x 128 cols
#pragma unroll
        for (int p = 0; p < 4; p++) {
            int r = (tid >> 5) + p * 8;
            int c4 = tid & 31;
            float4 v = *(const float4*)&B[(size_t)(k0 + r) * 256 + bn + c4 * 4];
            *(float4*)&Bs[r][c4 * 4] = v;
        }
        __syncthreads();

#pragma unroll
        for (int kk = 0; kk < TCK; kk += 8) {
            wmma::fragment<wmma::matrix_a, 16, 16, 8, wmma::precision::tf32, wmma::row_major> a_frag[2];
            wmma::fragment<wmma::matrix_b, 16, 16, 8, wmma::precision::tf32, wmma::row_major> b_frag[4];
#pragma unroll
            for (int i = 0; i < 2; i++) {
                wmma::load_matrix_sync(a_frag[i], &As[warp_m + i * 16][kk], TCK + 4);
#pragma unroll
                for (int t = 0; t < a_frag[i].num_elements; t++)
                    a_frag[i].x[t] = wmma::__float_to_tf32(a_frag[i].x[t]);
            }
#pragma unroll
            for (int j = 0; j < 4; j++) {
                wmma::load_matrix_sync(b_frag[j], &Bs[kk][warp_n + j * 16], TCN + 4);
#pragma unroll
                for (int t = 0; t < b_frag[j].num_elements; t++)
                    b_frag[j].x[t] = wmma::__float_to_tf32(b_frag[j].x[t]);
            }
#pragma unroll
            for (int i = 0; i < 2; i++)
#pragma unroll
                for (int j = 0; j < 4; j++)
                    wmma::mma_sync(c_frag[i][j], a_frag[i], b_frag[j], c_frag[i][j]);
        }
        __syncthreads();
    }

#pragma unroll
    for (int i = 0; i < 2; i++)
#pragma unroll
        for (int j = 0; j < 4; j++) {
            size_t off = (size_t)(bm + warp_m + i * 16) * 256 + bn + warp_n + j * 16;
            wmma::store_matrix_sync(&C[off], c_frag[i][j], 256, wmma::mem_row_major);
        }
}

// ---------------- layer 2 fused softmax+gather (no max) + bias/relu + pool ----------------
__global__ void k_gat2(const float* __restrict__ b2, const int* __restrict__ batch) {
    int n = blockIdx.x * 8 + (threadIdx.x >> 5);
    int lane = threadIdx.x & 31;
    if (n >= N_NODES) return;
    int row = g_rowstart[n], end = g_rowstart[n + 1];
    float alD = g_al_d2[n];

    float den = 0.f;
    float acc[8] = {0.f, 0.f, 0.f, 0.f, 0.f, 0.f, 0.f, 0.f};
    for (int j0 = row; j0 < end; j0 += 32) {
        int sj = (j0 + lane < end) ? __ldg(&g_csrc[j0 + lane]) : 0;
        int cnt = min(32, end - j0);
        for (int k = 0; k < cnt; k++) {
            int s = __shfl_sync(0xFFFFFFFFu, sj, k);
            float e = lrelu(__ldg(&g_al_s2[s]) + alD);
            float wgt = __expf(e);
            den += wgt;
            const float4* hp = (const float4*)&g_h2[s * C2 + lane * 8];
            float4 v0 = hp[0], v1 = hp[1];
            acc[0] += wgt * v0.x; acc[1] += wgt * v0.y;
            acc[2] += wgt * v0.z; acc[3] += wgt * v0.w;
            acc[4] += wgt * v1.x; acc[5] += wgt * v1.y;
            acc[6] += wgt * v1.z; acc[7] += wgt * v1.w;
        }
    }
    float inv = 1.f / (den + 1e-16f);
    int c0 = lane * 8;
    float4 o0, o1;
    o0.x = fmaxf(acc[0] * inv + b2[c0 + 0], 0.f);
    o0.y = fmaxf(acc[1] * inv + b2[c0 + 1], 0.f);
    o0.z = fmaxf(acc[2] * inv + b2[c0 + 2], 0.f);
    o0.w = fmaxf(acc[3] * inv + b2[c0 + 3], 0.f);
    o1.x = fmaxf(acc[4] * inv + b2[c0 + 4], 0.f);
    o1.y = fmaxf(acc[5] * inv + b2[c0 + 5], 0.f);
    o1.z = fmaxf(acc[6] * inv + b2[c0 + 6], 0.f);
    o1.w = fmaxf(acc[7] * inv + b2[c0 + 7], 0.f);
    int g = batch[n];
    red_add_v4(&g_pool[g * 256 + c0], o0);
    red_add_v4(&g_pool[g * 256 + c0 + 4], o1);
    if (lane == 0) atomicAdd(&g_cnt[g], 1.0f);
}

// ---------------- MLP head ----------------
__global__ void k_mlp1(const float* __restrict__ fw, const float* __restrict__ fb) {
    int g = blockIdx.x >> 2, q = blockIdx.x & 3;
    int t = threadIdx.x;
    __shared__ float grow[256];
    float inv = 1.0f / fmaxf(g_cnt[g], 1.0f);
    grow[t] = g_pool[g * 256 + t] * inv;
    __syncthreads();
    int col = q * 256 + t;
    float acc = fb[col];
#pragma unroll 8
    for (int k = 0; k < 256; k++) acc += grow[k] * fw[k * 1024 + col];
    g_fc1[g * 1024 + col] = fmaxf(acc, 0.f);
}

__global__ void k_mlp2(const float* __restrict__ fw, const float* __restrict__ fb,
                       float* __restrict__ out) {
    int g = blockIdx.x;
    int t = threadIdx.x; // 128
    __shared__ float row[1024];
    for (int k = t; k < 1024; k += 128) row[k] = g_fc1[g * 1024 + k];
    __syncthreads();
    float acc = fb[t];
#pragma unroll 8
    for (int k = 0; k < 1024; k++) acc += row[k] * fw[k * 128 + t];
    out[g * 128 + t] = acc;
}

// ---------------- host launcher ----------------
static void* sym(const void* s) {
    void* p = nullptr;
    cudaGetSymbolAddress(&p, s);
    return p;
}

extern "C" void kernel_launch(void* const* d_in, const int* in_sizes, int n_in,
                              void* d_out, int out_size) {
    const float* x      = (const float*)d_in[0];
    const int*   src    = (const int*)d_in[1];
    const int*   dst    = (const int*)d_in[2];
    const int*   batch  = (const int*)d_in[3];
    const float* W1     = (const float*)d_in[4];
    const float* a_src1 = (const float*)d_in[5];
    const float* a_dst1 = (const float*)d_in[6];
    const float* b1     = (const float*)d_in[7];
    const float* W2     = (const float*)d_in[8];
    const float* a_src2 = (const float*)d_in[9];
    const float* a_dst2 = (const float*)d_in[10];
    const float* b2     = (const float*)d_in[11];
    const float* fc1_w  = (const float*)d_in[12];
    const float* fc1_b  = (const float*)d_in[13];
    const float* fc2_w  = (const float*)d_in[14];
    const float* fc2_b  = (const float*)d_in[15];
    float* out = (float*)d_out;

    static bool attr_set = false;
    if (!attr_set) {
        cudaFuncSetAttribute(k_gemm1, cudaFuncAttributeMaxDynamicSharedMemorySize, G1_SMEM);
        attr_set = true;
    }

    cudaMemsetAsync(sym(g_deg),  0, N_NODES * sizeof(int));
    cudaMemsetAsync(sym(g_pool), 0, N_GRAPHS * 256 * sizeof(float));
    cudaMemsetAsync(sym(g_cnt),  0, N_GRAPHS * sizeof(float));

    // CSR build
    k_deg<<<(NT + 255) / 256, 256>>>(dst);
    k_scan<<<1, 1024>>>();
    k_fill<<<(NT + 255) / 256, 256>>>(src, dst);

    // precompute W2 @ a vectors (independent of everything above)
    k_wvec<<<32, 256>>>(W2, a_src2, a_dst2);

    // layer 1
    k_gemm1<<<(N_NODES + G1_M - 1) / G1_M, 256, G1_SMEM>>>(x, W1, a_src1, a_dst1);
    k_gat1<<<(N_NODES + 7) / 8, 256>>>(b1);

    // layer 2 (tf32 tensor cores, padded rows)
    float* d_o1 = (float*)sym(g_out1);
    float* d_h2 = (float*)sym(g_h2);
    dim3 g2(N_PAD / TCM, 256 / TCN);
    k_gemm2<<<g2, 256>>>(d_o1, W2, d_h2);
    k_gat2<<<(N_NODES + 7) / 8, 256>>>(b2, batch);

    // MLP
    k_mlp1<<<N_GRAPHS * 4, 256>>>(fc1_w, fc1_b);
    k_mlp2<<<N_GRAPHS, 128>>>(fc2_w, fc2_b, out);
}

// round 10
// speedup vs baseline: 4.6411x; 1.0942x over previous
#include <cuda_runtime.h>
#include <cuda_bf16.h>
#include <cuda_fp16.h>
#include <mma.h>
using namespace nvcuda;

#define N_NODES 50000
#define N_PAD   50048       // padded to multiple of 128 for the TC GEMM
#define N_EDGES 800000
#define NT      850000      // edges + self loops
#define N_GRAPHS 256
#define F_IN    41
#define C1      256
#define C2      256
#define NEG_SLOPE 0.2f

// ---------------- scratch (device globals) ----------------
__device__ __align__(16) __half g_h1h[N_NODES * C1];   // h1, fp16 (only gat1 reads)
__device__ float g_al_s1[N_NODES * 2];
__device__ float g_al_d1[N_NODES * 2];
__device__ __align__(16) float g_out1[N_PAD * C1];     // pad rows stay zero
__device__ __align__(16) float g_h2[N_PAD * C2];       // gemm2 fp32 output
__device__ __align__(16) __half g_h2h[N_NODES * C2];   // h2, fp16 (only gat2 reads)
__device__ float g_al_s2[N_NODES];
__device__ float g_al_d2[N_NODES];
__device__ __align__(16) float g_wvs[C2];
__device__ __align__(16) float g_wvd[C2];
__device__ __align__(16) float g_pool[N_GRAPHS * 256];
__device__ float g_cnt[N_GRAPHS];
__device__ float g_fc1[N_GRAPHS * 1024];
// CSR
__device__ int g_deg[N_NODES];
__device__ int g_rowstart[N_NODES + 1];
__device__ int g_cursor[N_NODES];
__device__ int g_csrc[NT];

__device__ __forceinline__ void red_add_v4(float* addr, float4 v) {
    asm volatile("red.global.add.v4.f32 [%0], {%1, %2, %3, %4};"
                 :: "l"(addr), "f"(v.x), "f"(v.y), "f"(v.z), "f"(v.w)
                 : "memory");
}
__device__ __forceinline__ float lrelu(float e) { return e > 0.f ? e : NEG_SLOPE * e; }

// ---------------- CSR build ----------------
__global__ void k_deg(const int* __restrict__ dst) {
    int i = blockIdx.x * blockDim.x + threadIdx.x;
    if (i >= NT) return;
    int d = (i < N_EDGES) ? dst[i] : i - N_EDGES;
    atomicAdd(&g_deg[d], 1);
}

// single-block exclusive scan over g_deg -> g_rowstart, g_cursor
__global__ void k_scan() {
    __shared__ int warp_sums[32];
    __shared__ int s_carry;
    int tid = threadIdx.x, lane = tid & 31, w = tid >> 5;
    if (tid == 0) s_carry = 0;
    __syncthreads();
    for (int base = 0; base < N_NODES; base += 1024) {
        int i = base + tid;
        int v = (i < N_NODES) ? g_deg[i] : 0;
        int incl = v;
#pragma unroll
        for (int o = 1; o < 32; o <<= 1) {
            int t = __shfl_up_sync(0xFFFFFFFFu, incl, o);
            if (lane >= o) incl += t;
        }
        if (lane == 31) warp_sums[w] = incl;
        __syncthreads();
        if (w == 0) {
            int s = warp_sums[lane];
#pragma unroll
            for (int o = 1; o < 32; o <<= 1) {
                int t = __shfl_up_sync(0xFFFFFFFFu, s, o);
                if (lane >= o) s += t;
            }
            warp_sums[lane] = s;    // inclusive over warps
        }
        __syncthreads();
        int warp_off = (w == 0) ? 0 : warp_sums[w - 1];
        int excl = s_carry + warp_off + incl - v;
        if (i < N_NODES) { g_rowstart[i] = excl; g_cursor[i] = excl; }
        __syncthreads();
        if (tid == 0) s_carry += warp_sums[31];
        __syncthreads();
    }
    if (tid == 0) g_rowstart[N_NODES] = NT;
}

__global__ void k_fill(const int* __restrict__ src, const int* __restrict__ dst) {
    int i = blockIdx.x * blockDim.x + threadIdx.x;
    if (i >= NT) return;
    int s, d;
    if (i < N_EDGES) { s = src[i]; d = dst[i]; } else { s = d = i - N_EDGES; }
    int p = atomicAdd(&g_cursor[d], 1);
    g_csrc[p] = s;
}

// ---------------- precompute w_s = W2 @ as2, w_d = W2 @ ad2 ----------------
__global__ void k_wvec(const float* __restrict__ W2, const float* __restrict__ as2,
                       const float* __restrict__ ad2) {
    int k = blockIdx.x * 8 + (threadIdx.x >> 5);
    int lane = threadIdx.x & 31;
    float s = 0.f, d = 0.f;
#pragma unroll
    for (int j = lane; j < 256; j += 32) {
        float w = W2[k * 256 + j];
        s += w * as2[j];
        d += w * ad2[j];
    }
#pragma unroll
    for (int o = 16; o > 0; o >>= 1) {
        s += __shfl_xor_sync(0xFFFFFFFFu, s, o);
        d += __shfl_xor_sync(0xFFFFFFFFu, d, o);
    }
    if (lane == 0) { g_wvs[k] = s; g_wvd[k] = d; }
}

// ---------------- layer 1 tiled GEMM + attention logits (fused) ----------------
// 64 nodes per 256-thread block; thread (tr,tc): rows tr*4..+3 x cols {tc+16i}.
// h1 stored as fp16 (only the gat1 gather consumes it).
#define G1_M 64
#define G1_SMEM (F_IN * C1 * 4 + G1_M * 43 * 4)
__global__ void __launch_bounds__(256) k_gemm1(const float* __restrict__ x,
                                               const float* __restrict__ W1,
                                               const float* __restrict__ a_s,
                                               const float* __restrict__ a_d) {
    extern __shared__ float sm[];
    float* W1s = sm;                                  // F_IN*C1
    float (*xs)[43] = (float (*)[43])(sm + F_IN * C1);
    int tid = threadIdx.x;
    int n0 = blockIdx.x * G1_M;

    for (int idx = tid; idx < (F_IN * C1) / 4; idx += 256)
        ((float4*)W1s)[idx] = ((const float4*)W1)[idx];
    for (int idx = tid; idx < G1_M * F_IN; idx += 256) {
        int r = idx / F_IN, c = idx % F_IN;
        int node = n0 + r;
        xs[r][c] = (node < N_NODES) ? x[node * F_IN + c] : 0.f;
    }
    __syncthreads();

    int tr = tid >> 4, tc = tid & 15;
    float acc[4][16];
#pragma unroll
    for (int j = 0; j < 4; j++)
#pragma unroll
        for (int i = 0; i < 16; i++) acc[j][i] = 0.f;

#pragma unroll 1
    for (int k = 0; k < F_IN; k++) {
        float a0 = xs[tr * 4 + 0][k];
        float a1 = xs[tr * 4 + 1][k];
        float a2 = xs[tr * 4 + 2][k];
        float a3 = xs[tr * 4 + 3][k];
        const float* wrow = &W1s[k * C1];
#pragma unroll
        for (int i = 0; i < 16; i++) {
            float b = wrow[tc + 16 * i];
            acc[0][i] += a0 * b;
            acc[1][i] += a1 * b;
            acc[2][i] += a2 * b;
            acc[3][i] += a3 * b;
        }
    }

    // store h1 (fp16) + per-thread partial logits (logits from fp32 accumulators)
    float sh0[4], sh1[4], dh0[4], dh1[4];
#pragma unroll
    for (int j = 0; j < 4; j++) { sh0[j] = sh1[j] = dh0[j] = dh1[j] = 0.f; }
#pragma unroll
    for (int i = 0; i < 16; i++) {
        int c = tc + 16 * i;
        float as = a_s[c], ad = a_d[c];
#pragma unroll
        for (int j = 0; j < 4; j++) {
            if (i < 8) { sh0[j] += acc[j][i] * as; dh0[j] += acc[j][i] * ad; }
            else       { sh1[j] += acc[j][i] * as; dh1[j] += acc[j][i] * ad; }
        }
    }
#pragma unroll
    for (int j = 0; j < 4; j++) {
        int node = n0 + tr * 4 + j;
        if (node < N_NODES) {
#pragma unroll
            for (int i = 0; i < 16; i++)
                g_h1h[node * C1 + tc + 16 * i] = __float2half_rn(acc[j][i]);
        }
    }
    // reduce across 16 tc lanes (xor <= 8 stays inside each 16-lane group)
#pragma unroll
    for (int o = 8; o > 0; o >>= 1) {
#pragma unroll
        for (int j = 0; j < 4; j++) {
            sh0[j] += __shfl_xor_sync(0xFFFFFFFFu, sh0[j], o);
            sh1[j] += __shfl_xor_sync(0xFFFFFFFFu, sh1[j], o);
            dh0[j] += __shfl_xor_sync(0xFFFFFFFFu, dh0[j], o);
            dh1[j] += __shfl_xor_sync(0xFFFFFFFFu, dh1[j], o);
        }
    }
    if (tc == 0) {
#pragma unroll
        for (int j = 0; j < 4; j++) {
            int node = n0 + tr * 4 + j;
            if (node < N_NODES) {
                g_al_s1[node * 2]     = sh0[j];  g_al_s1[node * 2 + 1] = sh1[j];
                g_al_d1[node * 2]     = dh0[j];  g_al_d1[node * 2 + 1] = dh1[j];
            }
        }
    }
}

// ---------------- layer 1 fused softmax+gather (fp16 h1) + al2 epilogue ----------------
__global__ void k_gat1(const float* __restrict__ b1) {
    int n = blockIdx.x * 8 + (threadIdx.x >> 5);
    int lane = threadIdx.x & 31;
    if (n >= N_NODES) return;
    int row = g_rowstart[n], end = g_rowstart[n + 1];
    int h = lane >> 4;                 // this lane's channels' head
    float alDh = g_al_d1[n * 2 + h];

    // single pass: exp weights + gather-accumulate (channels lane*8 .. lane*8+7)
    float den = 0.f;
    float acc[8] = {0.f, 0.f, 0.f, 0.f, 0.f, 0.f, 0.f, 0.f};
    for (int j0 = row; j0 < end; j0 += 32) {
        int sj = (j0 + lane < end) ? __ldg(&g_csrc[j0 + lane]) : 0;
        int cnt = min(32, end - j0);
        for (int k = 0; k < cnt; k++) {
            int s = __shfl_sync(0xFFFFFFFFu, sj, k);
            float e = lrelu(__ldg(&g_al_s1[s * 2 + h]) + alDh);
            float wgt = __expf(e);               // logits bounded, no max needed
            den += wgt;
            uint4 raw = *(const uint4*)&g_h1h[s * C1 + lane * 8];   // 8 halves
            __half2 hh[4];
            *(uint4*)hh = raw;
            float2 p0 = __half22float2(hh[0]);
            float2 p1 = __half22float2(hh[1]);
            float2 p2 = __half22float2(hh[2]);
            float2 p3 = __half22float2(hh[3]);
            acc[0] += wgt * p0.x; acc[1] += wgt * p0.y;
            acc[2] += wgt * p1.x; acc[3] += wgt * p1.y;
            acc[4] += wgt * p2.x; acc[5] += wgt * p2.y;
            acc[6] += wgt * p3.x; acc[7] += wgt * p3.y;
        }
    }
    float inv = 1.f / (den + 1e-16f);
    int c0 = lane * 8;
    float4 o0, o1;
    o0.x = fmaxf(acc[0] * inv + b1[c0 + 0], 0.f);
    o0.y = fmaxf(acc[1] * inv + b1[c0 + 1], 0.f);
    o0.z = fmaxf(acc[2] * inv + b1[c0 + 2], 0.f);
    o0.w = fmaxf(acc[3] * inv + b1[c0 + 3], 0.f);
    o1.x = fmaxf(acc[4] * inv + b1[c0 + 4], 0.f);
    o1.y = fmaxf(acc[5] * inv + b1[c0 + 5], 0.f);
    o1.z = fmaxf(acc[6] * inv + b1[c0 + 6], 0.f);
    o1.w = fmaxf(acc[7] * inv + b1[c0 + 7], 0.f);
    *(float4*)&g_out1[n * C1 + c0] = o0;
    *(float4*)&g_out1[n * C1 + c0 + 4] = o1;

    // fused al2: al_s2[n] = relu(out1[n]) . (W2 @ as2)  (likewise d)
    float4 ws0 = *(const float4*)&g_wvs[c0], ws1 = *(const float4*)&g_wvs[c0 + 4];
    float4 wd0 = *(const float4*)&g_wvd[c0], wd1 = *(const float4*)&g_wvd[c0 + 4];
    float ps = o0.x * ws0.x + o0.y * ws0.y + o0.z * ws0.z + o0.w * ws0.w
             + o1.x * ws1.x + o1.y * ws1.y + o1.z * ws1.z + o1.w * ws1.w;
    float pd = o0.x * wd0.x + o0.y * wd0.y + o0.z * wd0.z + o0.w * wd0.w
             + o1.x * wd1.x + o1.y * wd1.y + o1.z * wd1.z + o1.w * wd1.w;
#pragma unroll
    for (int o = 16; o > 0; o >>= 1) {
        ps += __shfl_xor_sync(0xFFFFFFFFu, ps, o);
        pd += __shfl_xor_sync(0xFFFFFFFFu, pd, o);
    }
    if (lane == 0) { g_al_s2[n] = ps; g_al_d2[n] = pd; }
}

// ---------------- tf32 tensor-core GEMM: g_h2 = g_out1(N_PAD x 256) @ W2(256 x 256) ----------------
#define TCM 128
#define TCN 128
#define TCK 32
__global__ void __launch_bounds__(256) k_gemm2(const float* __restrict__ A,
                                               const float* __restrict__ B,
                                               float* __restrict__ C) {
    __shared__ __align__(16) float As[TCM][TCK + 4];   // ldm 36 (mult of 4)
    __shared__ __align__(16) float Bs[TCK][TCN + 4];   // ldm 132
    int tid = threadIdx.x;
    int bm = blockIdx.x * TCM, bn = blockIdx.y * TCN;
    int wid = tid >> 5;
    int warp_m = (wid >> 1) * 32, warp_n = (wid & 1) * 64;

    wmma::fragment<wmma::accumulator, 16, 16, 8, float> c_frag[2][4];
#pragma unroll
    for (int i = 0; i < 2; i++)
#pragma unroll
        for (int j = 0; j < 4; j++) wmma::fill_fragment(c_frag[i][j], 0.f);

    for (int k0 = 0; k0 < 256; k0 += TCK) {
#pragma unroll
        for (int p = 0; p < 4; p++) {
            int r = (tid >> 3) + p * 32;
            int c4 = tid & 7;
            float4 v = *(const float4*)&A[(size_t)(bm + r) * 256 + k0 + c4 * 4];
            *(float4*)&As[r][c4 * 4] = v;
        }
#pragma unroll
        for (int p = 0; p < 4; p++) {
            int r = (tid >> 5) + p * 8;
            int c4 = tid & 31;
            float4 v = *(const float4*)&B[(size_t)(k0 + r) * 256 + bn + c4 * 4];
            *(float4*)&Bs[r][c4 * 4] = v;
        }
        __syncthreads();

#pragma unroll
        for (int kk = 0; kk < TCK; kk += 8) {
            wmma::fragment<wmma::matrix_a, 16, 16, 8, wmma::precision::tf32, wmma::row_major> a_frag[2];
            wmma::fragment<wmma::matrix_b, 16, 16, 8, wmma::precision::tf32, wmma::row_major> b_frag[4];
#pragma unroll
            for (int i = 0; i < 2; i++) {
                wmma::load_matrix_sync(a_frag[i], &As[warp_m + i * 16][kk], TCK + 4);
#pragma unroll
                for (int t = 0; t < a_frag[i].num_elements; t++)
                    a_frag[i].x[t] = wmma::__float_to_tf32(a_frag[i].x[t]);
            }
#pragma unroll
            for (int j = 0; j < 4; j++) {
                wmma::load_matrix_sync(b_frag[j], &Bs[kk][warp_n + j * 16], TCN + 4);
#pragma unroll
                for (int t = 0; t < b_frag[j].num_elements; t++)
                    b_frag[j].x[t] = wmma::__float_to_tf32(b_frag[j].x[t]);
            }
#pragma unroll
            for (int i = 0; i < 2; i++)
#pragma unroll
                for (int j = 0; j < 4; j++)
                    wmma::mma_sync(c_frag[i][j], a_frag[i], b_frag[j], c_frag[i][j]);
        }
        __syncthreads();
    }

#pragma unroll
    for (int i = 0; i < 2; i++)
#pragma unroll
        for (int j = 0; j < 4; j++) {
            size_t off = (size_t)(bm + warp_m + i * 16) * 256 + bn + warp_n + j * 16;
            wmma::store_matrix_sync(&C[off], c_frag[i][j], 256, wmma::mem_row_major);
        }
}

// ---------------- convert h2 fp32 -> fp16 for the gat2 gather ----------------
__global__ void k_h2half() {
    int idx = blockIdx.x * blockDim.x + threadIdx.x;     // one per 8 floats
    if (idx >= (N_NODES * C2) / 8) return;
    const float4* src = (const float4*)g_h2;
    float4 a = src[idx * 2], b = src[idx * 2 + 1];
    __half2 hh[4];
    hh[0] = __floats2half2_rn(a.x, a.y);
    hh[1] = __floats2half2_rn(a.z, a.w);
    hh[2] = __floats2half2_rn(b.x, b.y);
    hh[3] = __floats2half2_rn(b.z, b.w);
    *(uint4*)&g_h2h[idx * 8] = *(uint4*)hh;
}

// ---------------- layer 2 fused softmax+gather (fp16 h2) + bias/relu + pool ----------------
__global__ void k_gat2(const float* __restrict__ b2, const int* __restrict__ batch) {
    int n = blockIdx.x * 8 + (threadIdx.x >> 5);
    int lane = threadIdx.x & 31;
    if (n >= N_NODES) return;
    int row = g_rowstart[n], end = g_rowstart[n + 1];
    float alD = g_al_d2[n];

    float den = 0.f;
    float acc[8] = {0.f, 0.f, 0.f, 0.f, 0.f, 0.f, 0.f, 0.f};
    for (int j0 = row; j0 < end; j0 += 32) {
        int sj = (j0 + lane < end) ? __ldg(&g_csrc[j0 + lane]) : 0;
        int cnt = min(32, end - j0);
        for (int k = 0; k < cnt; k++) {
            int s = __shfl_sync(0xFFFFFFFFu, sj, k);
            float e = lrelu(__ldg(&g_al_s2[s]) + alD);
            float wgt = __expf(e);
            den += wgt;
            uint4 raw = *(const uint4*)&g_h2h[s * C2 + lane * 8];
            __half2 hh[4];
            *(uint4*)hh = raw;
            float2 p0 = __half22float2(hh[0]);
            float2 p1 = __half22float2(hh[1]);
            float2 p2 = __half22float2(hh[2]);
            float2 p3 = __half22float2(hh[3]);
            acc[0] += wgt * p0.x; acc[1] += wgt * p0.y;
            acc[2] += wgt * p1.x; acc[3] += wgt * p1.y;
            acc[4] += wgt * p2.x; acc[5] += wgt * p2.y;
            acc[6] += wgt * p3.x; acc[7] += wgt * p3.y;
        }
    }
    float inv = 1.f / (den + 1e-16f);
    int c0 = lane * 8;
    float4 o0, o1;
    o0.x = fmaxf(acc[0] * inv + b2[c0 + 0], 0.f);
    o0.y = fmaxf(acc[1] * inv + b2[c0 + 1], 0.f);
    o0.z = fmaxf(acc[2] * inv + b2[c0 + 2], 0.f);
    o0.w = fmaxf(acc[3] * inv + b2[c0 + 3], 0.f);
    o1.x = fmaxf(acc[4] * inv + b2[c0 + 4], 0.f);
    o1.y = fmaxf(acc[5] * inv + b2[c0 + 5], 0.f);
    o1.z = fmaxf(acc[6] * inv + b2[c0 + 6], 0.f);
    o1.w = fmaxf(acc[7] * inv + b2[c0 + 7], 0.f);
    int g = batch[n];
    red_add_v4(&g_pool[g * 256 + c0], o0);
    red_add_v4(&g_pool[g * 256 + c0 + 4], o1);
    if (lane == 0) atomicAdd(&g_cnt[g], 1.0f);
}

// ---------------- MLP head ----------------
__global__ void k_mlp1(const float* __restrict__ fw, const float* __restrict__ fb) {
    int g = blockIdx.x >> 2, q = blockIdx.x & 3;
    int t = threadIdx.x;
    __shared__ float grow[256];
    float inv = 1.0f / fmaxf(g_cnt[g], 1.0f);
    grow[t] = g_pool[g * 256 + t] * inv;
    __syncthreads();
    int col = q * 256 + t;
    float acc = fb[col];
#pragma unroll 8
    for (int k = 0; k < 256; k++) acc += grow[k] * fw[k * 1024 + col];
    g_fc1[g * 1024 + col] = fmaxf(acc, 0.f);
}

__global__ void k_mlp2(const float* __restrict__ fw, const float* __restrict__ fb,
                       float* __restrict__ out) {
    int g = blockIdx.x;
    int t = threadIdx.x; // 128
    __shared__ float row[1024];
    for (int k = t; k < 1024; k += 128) row[k] = g_fc1[g * 1024 + k];
    __syncthreads();
    float acc = fb[t];
#pragma unroll 8
    for (int k = 0; k < 1024; k++) acc += row[k] * fw[k * 128 + t];
    out[g * 128 + t] = acc;
}

// ---------------- host launcher ----------------
static void* sym(const void* s) {
    void* p = nullptr;
    cudaGetSymbolAddress(&p, s);
    return p;
}

extern "C" void kernel_launch(void* const* d_in, const int* in_sizes, int n_in,
                              void* d_out, int out_size) {
    const float* x      = (const float*)d_in[0];
    const int*   src    = (const int*)d_in[1];
    const int*   dst    = (const int*)d_in[2];
    const int*   batch  = (const int*)d_in[3];
    const float* W1     = (const float*)d_in[4];
    const float* a_src1 = (const float*)d_in[5];
    const float* a_dst1 = (const float*)d_in[6];
    const float* b1     = (const float*)d_in[7];
    const float* W2     = (const float*)d_in[8];
    const float* a_src2 = (const float*)d_in[9];
    const float* a_dst2 = (const float*)d_in[10];
    const float* b2     = (const float*)d_in[11];
    const float* fc1_w  = (const float*)d_in[12];
    const float* fc1_b  = (const float*)d_in[13];
    const float* fc2_w  = (const float*)d_in[14];
    const float* fc2_b  = (const float*)d_in[15];
    float* out = (float*)d_out;

    static bool attr_set = false;
    if (!attr_set) {
        cudaFuncSetAttribute(k_gemm1, cudaFuncAttributeMaxDynamicSharedMemorySize, G1_SMEM);
        attr_set = true;
    }

    cudaMemsetAsync(sym(g_deg),  0, N_NODES * sizeof(int));
    cudaMemsetAsync(sym(g_pool), 0, N_GRAPHS * 256 * sizeof(float));
    cudaMemsetAsync(sym(g_cnt),  0, N_GRAPHS * sizeof(float));

    // CSR build
    k_deg<<<(NT + 255) / 256, 256>>>(dst);
    k_scan<<<1, 1024>>>();
    k_fill<<<(NT + 255) / 256, 256>>>(src, dst);

    // precompute W2 @ a vectors (independent of everything above)
    k_wvec<<<32, 256>>>(W2, a_src2, a_dst2);

    // layer 1
    k_gemm1<<<(N_NODES + G1_M - 1) / G1_M, 256, G1_SMEM>>>(x, W1, a_src1, a_dst1);
    k_gat1<<<(N_NODES + 7) / 8, 256>>>(b1);

    // layer 2 (tf32 tensor cores, padded rows), then fp16 copy for the gather
    float* d_o1 = (float*)sym(g_out1);
    float* d_h2 = (float*)sym(g_h2);
    dim3 g2(N_PAD / TCM, 256 / TCN);
    k_gemm2<<<g2, 256>>>(d_o1, W2, d_h2);
    k_h2half<<<(N_NODES * C2 / 8 + 255) / 256, 256>>>();
    k_gat2<<<(N_NODES + 7) / 8, 256>>>(b2, batch);

    // MLP
    k_mlp1<<<N_GRAPHS * 4, 256>>>(fc1_w, fc1_b);
    k_mlp2<<<N_GRAPHS, 128>>>(fc2_w, fc2_b, out);
}

// round 12
// speedup vs baseline: 4.8465x; 1.0443x over previous
#include <cuda_runtime.h>
#include <cuda_bf16.h>
#include <cuda_fp16.h>
#include <mma.h>
using namespace nvcuda;

#define N_NODES 50000
#define N_PAD   50048       // padded to multiple of 128 for the TC GEMM
#define N_EDGES 800000
#define NT      850000      // edges + self loops
#define N_GRAPHS 256
#define F_IN    41
#define C1      256
#define C2      256
#define NEG_SLOPE 0.2f

// ---------------- scratch (device globals) ----------------
__device__ __align__(16) __half g_h1h[N_NODES * C1];   // h1, fp16 (only gat1 reads)
__device__ float g_al_s1[N_NODES * 2];
__device__ float g_al_d1[N_NODES * 2];
__device__ __align__(16) float g_out1[N_PAD * C1];     // pad rows stay zero
__device__ __align__(16) __half g_h2h[N_PAD * C2];     // h2, fp16 (gemm2 writes, gat2 reads)
__device__ float g_al_s2[N_NODES];
__device__ float g_al_d2[N_NODES];
__device__ __align__(16) float g_wvs[C2];
__device__ __align__(16) float g_wvd[C2];
__device__ __align__(16) float g_pool[N_GRAPHS * 256];
__device__ float g_cnt[N_GRAPHS];
__device__ float g_fc1[N_GRAPHS * 1024];
// CSR
__device__ int g_deg[N_NODES];
__device__ int g_rowstart[N_NODES + 1];
__device__ int g_cursor[N_NODES];
__device__ int g_csrc[NT];

__device__ __forceinline__ void red_add_v4(float* addr, float4 v) {
    asm volatile("red.global.add.v4.f32 [%0], {%1, %2, %3, %4};"
                 :: "l"(addr), "f"(v.x), "f"(v.y), "f"(v.z), "f"(v.w)
                 : "memory");
}
__device__ __forceinline__ float lrelu(float e) { return e > 0.f ? e : NEG_SLOPE * e; }

// unpack 8 halves (uint4) and FMA into acc with weight w
__device__ __forceinline__ void fma8h(float* acc, uint4 raw, float w) {
    __half2 hh[4];
    *(uint4*)hh = raw;
    float2 p0 = __half22float2(hh[0]);
    float2 p1 = __half22float2(hh[1]);
    float2 p2 = __half22float2(hh[2]);
    float2 p3 = __half22float2(hh[3]);
    acc[0] += w * p0.x; acc[1] += w * p0.y;
    acc[2] += w * p1.x; acc[3] += w * p1.y;
    acc[4] += w * p2.x; acc[5] += w * p2.y;
    acc[6] += w * p3.x; acc[7] += w * p3.y;
}

// ---------------- CSR build ----------------
__global__ void k_deg(const int* __restrict__ dst) {
    int i = blockIdx.x * blockDim.x + threadIdx.x;
    if (i >= NT) return;
    int d = (i < N_EDGES) ? dst[i] : i - N_EDGES;
    atomicAdd(&g_deg[d], 1);
}

// single-block exclusive scan over g_deg -> g_rowstart, g_cursor
__global__ void k_scan() {
    __shared__ int warp_sums[32];
    __shared__ int s_carry;
    int tid = threadIdx.x, lane = tid & 31, w = tid >> 5;
    if (tid == 0) s_carry = 0;
    __syncthreads();
    for (int base = 0; base < N_NODES; base += 1024) {
        int i = base + tid;
        int v = (i < N_NODES) ? g_deg[i] : 0;
        int incl = v;
#pragma unroll
        for (int o = 1; o < 32; o <<= 1) {
            int t = __shfl_up_sync(0xFFFFFFFFu, incl, o);
            if (lane >= o) incl += t;
        }
        if (lane == 31) warp_sums[w] = incl;
        __syncthreads();
        if (w == 0) {
            int s = warp_sums[lane];
#pragma unroll
            for (int o = 1; o < 32; o <<= 1) {
                int t = __shfl_up_sync(0xFFFFFFFFu, s, o);
                if (lane >= o) s += t;
            }
            warp_sums[lane] = s;    // inclusive over warps
        }
        __syncthreads();
        int warp_off = (w == 0) ? 0 : warp_sums[w - 1];
        int excl = s_carry + warp_off + incl - v;
        if (i < N_NODES) { g_rowstart[i] = excl; g_cursor[i] = excl; }
        __syncthreads();
        if (tid == 0) s_carry += warp_sums[31];
        __syncthreads();
    }
    if (tid == 0) g_rowstart[N_NODES] = NT;
}

__global__ void k_fill(const int* __restrict__ src, const int* __restrict__ dst) {
    int i = blockIdx.x * blockDim.x + threadIdx.x;
    if (i >= NT) return;
    int s, d;
    if (i < N_EDGES) { s = src[i]; d = dst[i]; } else { s = d = i - N_EDGES; }
    int p = atomicAdd(&g_cursor[d], 1);
    g_csrc[p] = s;
}

// ---------------- precompute w_s = W2 @ as2, w_d = W2 @ ad2 ----------------
__global__ void k_wvec(const float* __restrict__ W2, const float* __restrict__ as2,
                       const float* __restrict__ ad2) {
    int k = blockIdx.x * 8 + (threadIdx.x >> 5);
    int lane = threadIdx.x & 31;
    float s = 0.f, d = 0.f;
#pragma unroll
    for (int j = lane; j < 256; j += 32) {
        float w = W2[k * 256 + j];
        s += w * as2[j];
        d += w * ad2[j];
    }
#pragma unroll
    for (int o = 16; o > 0; o >>= 1) {
        s += __shfl_xor_sync(0xFFFFFFFFu, s, o);
        d += __shfl_xor_sync(0xFFFFFFFFu, d, o);
    }
    if (lane == 0) { g_wvs[k] = s; g_wvd[k] = d; }
}

// ---------------- layer 1 tiled GEMM + attention logits (fused) ----------------
// 64 nodes per 256-thread block; thread (tr,tc): rows tr*4..+3 x cols {tc+16i}.
#define G1_M 64
#define G1_SMEM (F_IN * C1 * 4 + G1_M * 43 * 4)
__global__ void __launch_bounds__(256) k_gemm1(const float* __restrict__ x,
                                               const float* __restrict__ W1,
                                               const float* __restrict__ a_s,
                                               const float* __restrict__ a_d) {
    extern __shared__ float sm[];
    float* W1s = sm;                                  // F_IN*C1
    float (*xs)[43] = (float (*)[43])(sm + F_IN * C1);
    int tid = threadIdx.x;
    int n0 = blockIdx.x * G1_M;

    for (int idx = tid; idx < (F_IN * C1) / 4; idx += 256)
        ((float4*)W1s)[idx] = ((const float4*)W1)[idx];
    for (int idx = tid; idx < G1_M * F_IN; idx += 256) {
        int r = idx / F_IN, c = idx % F_IN;
        int node = n0 + r;
        xs[r][c] = (node < N_NODES) ? x[node * F_IN + c] : 0.f;
    }
    __syncthreads();

    int tr = tid >> 4, tc = tid & 15;
    float acc[4][16];
#pragma unroll
    for (int j = 0; j < 4; j++)
#pragma unroll
        for (int i = 0; i < 16; i++) acc[j][i] = 0.f;

#pragma unroll 1
    for (int k = 0; k < F_IN; k++) {
        float a0 = xs[tr * 4 + 0][k];
        float a1 = xs[tr * 4 + 1][k];
        float a2 = xs[tr * 4 + 2][k];
        float a3 = xs[tr * 4 + 3][k];
        const float* wrow = &W1s[k * C1];
#pragma unroll
        for (int i = 0; i < 16; i++) {
            float b = wrow[tc + 16 * i];
            acc[0][i] += a0 * b;
            acc[1][i] += a1 * b;
            acc[2][i] += a2 * b;
            acc[3][i] += a3 * b;
        }
    }

    // store h1 (fp16) + per-thread partial logits (logits from fp32 accumulators)
    float sh0[4], sh1[4], dh0[4], dh1[4];
#pragma unroll
    for (int j = 0; j < 4; j++) { sh0[j] = sh1[j] = dh0[j] = dh1[j] = 0.f; }
#pragma unroll
    for (int i = 0; i < 16; i++) {
        int c = tc + 16 * i;
        float as = a_s[c], ad = a_d[c];
#pragma unroll
        for (int j = 0; j < 4; j++) {
            if (i < 8) { sh0[j] += acc[j][i] * as; dh0[j] += acc[j][i] * ad; }
            else       { sh1[j] += acc[j][i] * as; dh1[j] += acc[j][i] * ad; }
        }
    }
#pragma unroll
    for (int j = 0; j < 4; j++) {
        int node = n0 + tr * 4 + j;
        if (node < N_NODES) {
#pragma unroll
            for (int i = 0; i < 16; i++)
                g_h1h[node * C1 + tc + 16 * i] = __float2half_rn(acc[j][i]);
        }
    }
#pragma unroll
    for (int o = 8; o > 0; o >>= 1) {
#pragma unroll
        for (int j = 0; j < 4; j++) {
            sh0[j] += __shfl_xor_sync(0xFFFFFFFFu, sh0[j], o);
            sh1[j] += __shfl_xor_sync(0xFFFFFFFFu, sh1[j], o);
            dh0[j] += __shfl_xor_sync(0xFFFFFFFFu, dh0[j], o);
            dh1[j] += __shfl_xor_sync(0xFFFFFFFFu, dh1[j], o);
        }
    }
    if (tc == 0) {
#pragma unroll
        for (int j = 0; j < 4; j++) {
            int node = n0 + tr * 4 + j;
            if (node < N_NODES) {
                g_al_s1[node * 2]     = sh0[j];  g_al_s1[node * 2 + 1] = sh1[j];
                g_al_d1[node * 2]     = dh0[j];  g_al_d1[node * 2 + 1] = dh1[j];
            }
        }
    }
}

// ---------------- layer 1 fused softmax+gather (fp16 h1, 2-way ILP) + al2 epilogue ----------------
__global__ void k_gat1(const float* __restrict__ b1) {
    int n = blockIdx.x * 8 + (threadIdx.x >> 5);
    int lane = threadIdx.x & 31;
    if (n >= N_NODES) return;
    int row = g_rowstart[n], end = g_rowstart[n + 1];
    int h = lane >> 4;
    float alDh = g_al_d1[n * 2 + h];

    float den = 0.f;
    float acc[8] = {0.f, 0.f, 0.f, 0.f, 0.f, 0.f, 0.f, 0.f};
    for (int j0 = row; j0 < end; j0 += 32) {
        int sj = (j0 + lane < end) ? __ldg(&g_csrc[j0 + lane]) : 0;
        int cnt = min(32, end - j0);
        int k = 0;
        for (; k + 1 < cnt; k += 2) {
            int s0 = __shfl_sync(0xFFFFFFFFu, sj, k);
            int s1 = __shfl_sync(0xFFFFFFFFu, sj, k + 1);
            float e0 = lrelu(__ldg(&g_al_s1[s0 * 2 + h]) + alDh);
            float e1 = lrelu(__ldg(&g_al_s1[s1 * 2 + h]) + alDh);
            uint4 r0 = *(const uint4*)&g_h1h[s0 * C1 + lane * 8];
            uint4 r1 = *(const uint4*)&g_h1h[s1 * C1 + lane * 8];
            float w0 = __expf(e0), w1 = __expf(e1);
            den += w0 + w1;
            fma8h(acc, r0, w0);
            fma8h(acc, r1, w1);
        }
        if (k < cnt) {
            int s = __shfl_sync(0xFFFFFFFFu, sj, k);
            float e = lrelu(__ldg(&g_al_s1[s * 2 + h]) + alDh);
            float w = __expf(e);
            den += w;
            fma8h(acc, *(const uint4*)&g_h1h[s * C1 + lane * 8], w);
        }
    }
    float inv = 1.f / (den + 1e-16f);
    int c0 = lane * 8;
    float4 o0, o1;
    o0.x = fmaxf(acc[0] * inv + b1[c0 + 0], 0.f);
    o0.y = fmaxf(acc[1] * inv + b1[c0 + 1], 0.f);
    o0.z = fmaxf(acc[2] * inv + b1[c0 + 2], 0.f);
    o0.w = fmaxf(acc[3] * inv + b1[c0 + 3], 0.f);
    o1.x = fmaxf(acc[4] * inv + b1[c0 + 4], 0.f);
    o1.y = fmaxf(acc[5] * inv + b1[c0 + 5], 0.f);
    o1.z = fmaxf(acc[6] * inv + b1[c0 + 6], 0.f);
    o1.w = fmaxf(acc[7] * inv + b1[c0 + 7], 0.f);
    *(float4*)&g_out1[n * C1 + c0] = o0;
    *(float4*)&g_out1[n * C1 + c0 + 4] = o1;

    // fused al2: al_s2[n] = relu(out1[n]) . (W2 @ as2)  (likewise d)
    float4 ws0 = *(const float4*)&g_wvs[c0], ws1 = *(const float4*)&g_wvs[c0 + 4];
    float4 wd0 = *(const float4*)&g_wvd[c0], wd1 = *(const float4*)&g_wvd[c0 + 4];
    float ps = o0.x * ws0.x + o0.y * ws0.y + o0.z * ws0.z + o0.w * ws0.w
             + o1.x * ws1.x + o1.y * ws1.y + o1.z * ws1.z + o1.w * ws1.w;
    float pd = o0.x * wd0.x + o0.y * wd0.y + o0.z * wd0.z + o0.w * wd0.w
             + o1.x * wd1.x + o1.y * wd1.y + o1.z * wd1.z + o1.w * wd1.w;
#pragma unroll
    for (int o = 16; o > 0; o >>= 1) {
        ps += __shfl_xor_sync(0xFFFFFFFFu, ps, o);
        pd += __shfl_xor_sync(0xFFFFFFFFu, pd, o);
    }
    if (lane == 0) { g_al_s2[n] = ps; g_al_d2[n] = pd; }
}

// ---------------- tf32 tensor-core GEMM, fp16 output: g_h2h = g_out1 @ W2 ----------------
#define TCM 128
#define TCN 128
#define TCK 32
__global__ void __launch_bounds__(256) k_gemm2(const float* __restrict__ A,
                                               const float* __restrict__ B,
                                               __half* __restrict__ C) {
    __shared__ __align__(16) float As[TCM][TCK + 4];   // 18.4 KB
    __shared__ __align__(16) float Bs[TCK][TCN + 4];   // 16.9 KB
    __shared__ __align__(16) float Epi[8][256];        // 8 KB: per-warp 16x16 patch
    int tid = threadIdx.x;
    int bm = blockIdx.x * TCM, bn = blockIdx.y * TCN;
    int wid = tid >> 5, lane = tid & 31;
    int warp_m = (wid >> 1) * 32, warp_n = (wid & 1) * 64;

    wmma::fragment<wmma::accumulator, 16, 16, 8, float> c_frag[2][4];
#pragma unroll
    for (int i = 0; i < 2; i++)
#pragma unroll
        for (int j = 0; j < 4; j++) wmma::fill_fragment(c_frag[i][j], 0.f);

    for (int k0 = 0; k0 < 256; k0 += TCK) {
#pragma unroll
        for (int p = 0; p < 4; p++) {
            int r = (tid >> 3) + p * 32;
            int c4 = tid & 7;
            float4 v = *(const float4*)&A[(size_t)(bm + r) * 256 + k0 + c4 * 4];
            *(float4*)&As[r][c4 * 4] = v;
        }
#pragma unroll
        for (int p = 0; p < 4; p++) {
            int r = (tid >> 5) + p * 8;
            int c4 = tid & 31;
            float4 v = *(const float4*)&B[(size_t)(k0 + r) * 256 + bn + c4 * 4];
            *(float4*)&Bs[r][c4 * 4] = v;
        }
        __syncthreads();

#pragma unroll
        for (int kk = 0; kk < TCK; kk += 8) {
            wmma::fragment<wmma::matrix_a, 16, 16, 8, wmma::precision::tf32, wmma::row_major> a_frag[2];
            wmma::fragment<wmma::matrix_b, 16, 16, 8, wmma::precision::tf32, wmma::row_major> b_frag[4];
#pragma unroll
            for (int i = 0; i < 2; i++) {
                wmma::load_matrix_sync(a_frag[i], &As[warp_m + i * 16][kk], TCK + 4);
#pragma unroll
                for (int t = 0; t < a_frag[i].num_elements; t++)
                    a_frag[i].x[t] = wmma::__float_to_tf32(a_frag[i].x[t]);
            }
#pragma unroll
            for (int j = 0; j < 4; j++) {
                wmma::load_matrix_sync(b_frag[j], &Bs[kk][warp_n + j * 16], TCN + 4);
#pragma unroll
                for (int t = 0; t < b_frag[j].num_elements; t++)
                    b_frag[j].x[t] = wmma::__float_to_tf32(b_frag[j].x[t]);
            }
#pragma unroll
            for (int i = 0; i < 2; i++)
#pragma unroll
                for (int j = 0; j < 4; j++)
                    wmma::mma_sync(c_frag[i][j], a_frag[i], b_frag[j], c_frag[i][j]);
        }
        __syncthreads();
    }

    // epilogue: stage each 16x16 fragment through smem, convert to fp16, store
    float* patch = &Epi[wid][0];
    int er = lane >> 1, ec = (lane & 1) * 8;   // each lane: 8 floats of one row
#pragma unroll
    for (int i = 0; i < 2; i++)
#pragma unroll
        for (int j = 0; j < 4; j++) {
            wmma::store_matrix_sync(patch, c_frag[i][j], 16, wmma::mem_row_major);
            __syncwarp();
            float4 a = *(float4*)&patch[er * 16 + ec];
            float4 b = *(float4*)&patch[er * 16 + ec + 4];
            __half2 hh[4];
            hh[0] = __floats2half2_rn(a.x, a.y);
            hh[1] = __floats2half2_rn(a.z, a.w);
            hh[2] = __floats2half2_rn(b.x, b.y);
            hh[3] = __floats2half2_rn(b.z, b.w);
            size_t off = (size_t)(bm + warp_m + i * 16 + er) * 256 + bn + warp_n + j * 16 + ec;
            *(uint4*)&C[off] = *(uint4*)hh;
            __syncwarp();
        }
}

// ---------------- layer 2 fused softmax+gather (fp16 h2, 2-way ILP) + bias/relu + pool ----------------
__global__ void k_gat2(const float* __restrict__ b2, const int* __restrict__ batch) {
    int n = blockIdx.x * 8 + (threadIdx.x >> 5);
    int lane = threadIdx.x & 31;
    if (n >= N_NODES) return;
    int row = g_rowstart[n], end = g_rowstart[n + 1];
    float alD = g_al_d2[n];

    float den = 0.f;
    float acc[8] = {0.f, 0.f, 0.f, 0.f, 0.f, 0.f, 0.f, 0.f};
    for (int j0 = row; j0 < end; j0 += 32) {
        int sj = (j0 + lane < end) ? __ldg(&g_csrc[j0 + lane]) : 0;
        int cnt = min(32, end - j0);
        int k = 0;
        for (; k + 1 < cnt; k += 2) {
            int s0 = __shfl_sync(0xFFFFFFFFu, sj, k);
            int s1 = __shfl_sync(0xFFFFFFFFu, sj, k + 1);
            float e0 = lrelu(__ldg(&g_al_s2[s0]) + alD);
            float e1 = lrelu(__ldg(&g_al_s2[s1]) + alD);
            uint4 r0 = *(const uint4*)&g_h2h[s0 * C2 + lane * 8];
            uint4 r1 = *(const uint4*)&g_h2h[s1 * C2 + lane * 8];
            float w0 = __expf(e0), w1 = __expf(e1);
            den += w0 + w1;
            fma8h(acc, r0, w0);
            fma8h(acc, r1, w1);
        }
        if (k < cnt) {
            int s = __shfl_sync(0xFFFFFFFFu, sj, k);
            float e = lrelu(__ldg(&g_al_s2[s]) + alD);
            float w = __expf(e);
            den += w;
            fma8h(acc, *(const uint4*)&g_h2h[s * C2 + lane * 8], w);
        }
    }
    float inv = 1.f / (den + 1e-16f);
    int c0 = lane * 8;
    float4 o0, o1;
    o0.x = fmaxf(acc[0] * inv + b2[c0 + 0], 0.f);
    o0.y = fmaxf(acc[1] * inv + b2[c0 + 1], 0.f);
    o0.z = fmaxf(acc[2] * inv + b2[c0 + 2], 0.f);
    o0.w = fmaxf(acc[3] * inv + b2[c0 + 3], 0.f);
    o1.x = fmaxf(acc[4] * inv + b2[c0 + 4], 0.f);
    o1.y = fmaxf(acc[5] * inv + b2[c0 + 5], 0.f);
    o1.z = fmaxf(acc[6] * inv + b2[c0 + 6], 0.f);
    o1.w = fmaxf(acc[7] * inv + b2[c0 + 7], 0.f);
    int g = batch[n];
    red_add_v4(&g_pool[g * 256 + c0], o0);
    red_add_v4(&g_pool[g * 256 + c0 + 4], o1);
    if (lane == 0) atomicAdd(&g_cnt[g], 1.0f);
}

// ---------------- MLP head ----------------
__global__ void k_mlp1(const float* __restrict__ fw, const float* __restrict__ fb) {
    int g = blockIdx.x >> 2, q = blockIdx.x & 3;
    int t = threadIdx.x;
    __shared__ float grow[256];
    float inv = 1.0f / fmaxf(g_cnt[g], 1.0f);
    grow[t] = g_pool[g * 256 + t] * inv;
    __syncthreads();
    int col = q * 256 + t;
    float acc = fb[col];
#pragma unroll 8
    for (int k = 0; k < 256; k++) acc += grow[k] * fw[k * 1024 + col];
    g_fc1[g * 1024 + col] = fmaxf(acc, 0.f);
}

__global__ void k_mlp2(const float* __restrict__ fw, const float* __restrict__ fb,
                       float* __restrict__ out) {
    int g = blockIdx.x;
    int t = threadIdx.x; // 128
    __shared__ float row[1024];
    for (int k = t; k < 1024; k += 128) row[k] = g_fc1[g * 1024 + k];
    __syncthreads();
    float acc = fb[t];
#pragma unroll 8
    for (int k = 0; k < 1024; k++) acc += row[k] * fw[k * 128 + t];
    out[g * 128 + t] = acc;
}

// ---------------- host launcher ----------------
static void* sym(const void* s) {
    void* p = nullptr;
    cudaGetSymbolAddress(&p, s);
    return p;
}

extern "C" void kernel_launch(void* const* d_in, const int* in_sizes, int n_in,
                              void* d_out, int out_size) {
    const float* x      = (const float*)d_in[0];
    const int*   src    = (const int*)d_in[1];
    const int*   dst    = (const int*)d_in[2];
    const int*   batch  = (const int*)d_in[3];
    const float* W1     = (const float*)d_in[4];
    const float* a_src1 = (const float*)d_in[5];
    const float* a_dst1 = (const float*)d_in[6];
    const float* b1     = (const float*)d_in[7];
    const float* W2     = (const float*)d_in[8];
    const float* a_src2 = (const float*)d_in[9];
    const float* a_dst2 = (const float*)d_in[10];
    const float* b2     = (const float*)d_in[11];
    const float* fc1_w  = (const float*)d_in[12];
    const float* fc1_b  = (const float*)d_in[13];
    const float* fc2_w  = (const float*)d_in[14];
    const float* fc2_b  = (const float*)d_in[15];
    float* out = (float*)d_out;

    static bool attr_set = false;
    if (!attr_set) {
        cudaFuncSetAttribute(k_gemm1, cudaFuncAttributeMaxDynamicSharedMemorySize, G1_SMEM);
        attr_set = true;
    }

    cudaMemsetAsync(sym(g_deg),  0, N_NODES * sizeof(int));
    cudaMemsetAsync(sym(g_pool), 0, N_GRAPHS * 256 * sizeof(float));
    cudaMemsetAsync(sym(g_cnt),  0, N_GRAPHS * sizeof(float));

    // CSR build
    k_deg<<<(NT + 255) / 256, 256>>>(dst);
    k_scan<<<1, 1024>>>();
    k_fill<<<(NT + 255) / 256, 256>>>(src, dst);

    // precompute W2 @ a vectors (independent of everything above)
    k_wvec<<<32, 256>>>(W2, a_src2, a_dst2);

    // layer 1
    k_gemm1<<<(N_NODES + G1_M - 1) / G1_M, 256, G1_SMEM>>>(x, W1, a_src1, a_dst1);
    k_gat1<<<(N_NODES + 7) / 8, 256>>>(b1);

    // layer 2 (tf32 tensor cores, fp16 output, padded rows)
    float* d_o1 = (float*)sym(g_out1);
    __half* d_h2h = (__half*)sym(g_h2h);
    dim3 g2(N_PAD / TCM, 256 / TCN);
    k_gemm2<<<g2, 256>>>(d_o1, W2, d_h2h);
    k_gat2<<<(N_NODES + 7) / 8, 256>>>(b2, batch);

    // MLP
    k_mlp1<<<N_GRAPHS * 4, 256>>>(fc1_w, fc1_b);
    k_mlp2<<<N_GRAPHS, 128>>>(fc2_w, fc2_b, out);
}